// round 14
// baseline (speedup 1.0000x reference)
#include <cuda_runtime.h>
#include <cuda_fp16.h>
#include <math.h>
#include <stdint.h>

#define Bq   4
#define Sq   2048
#define Hq   512
#define NHq  4
#define HDq  128
#define FFNq 2048
#define Lq   3
#define BSq  (Bq*Sq)
#define CHq  128
#define NCq  (Sq/CHq)
#define EPSq 1e-5f
#define PA   20
#define PAsm 132
#define PH   40
#define QS   2048
#define KOFF 512
#define VOFF 1024
#define GOFF 1536

// fp32 buffers
__device__ float g_Y[BSq*Hq];
__device__ float g_X[BSq*Hq];
__device__ float g_M[Bq*NHq*NCq*HDq*HDq];
__device__ float g_St[Bq*NHq*NCq*HDq*HDq];
__device__ float2 g_xposT[2*Sq*64];
// fp16 buffers
__device__ __half g_QKVGh[BSq*QS];
__device__ __half g_XnH[BSq*Hq];
__device__ __half g_GatedH[BSq*Hq];
__device__ __half g_HnH[BSq*Hq];
__device__ __half g_HfH[BSq*FFNq];
__device__ __half g_XH[BSq*Hq];
// fp16 weights [N][K]
__device__ __half g_Wcat[Lq*QS*Hq];
__device__ __half g_WOTh[Lq*Hq*Hq];
__device__ __half g_W1Th[Lq*FFNq*Hq];
__device__ __half g_W2Th[Lq*Hq*FFNq];

__device__ __forceinline__ float gamma_of(int n) {
    double lg = -3.4657359027997265 + (double)n * (-0.9241962407465937);
    return (float)(1.0 - exp(lg));
}
__device__ __forceinline__ uint32_t f2tf(float x) {
    uint32_t y;
    asm("cvt.rna.tf32.f32 %0, %1;" : "=r"(y) : "f"(x));
    return y;
}
__device__ __forceinline__ uint32_t smem_u32(const void* p) {
    uint32_t a;
    asm("{ .reg .u64 t; cvta.to.shared.u64 t, %1; cvt.u32.u64 %0, t; }" : "=r"(a) : "l"(p));
    return a;
}
__device__ __forceinline__ void cp16(uint32_t saddr, const void* g) {
    asm volatile("cp.async.ca.shared.global [%0], [%1], 16;" :: "r"(saddr), "l"(g));
}
#define CP_COMMIT() asm volatile("cp.async.commit_group;" ::: "memory")
#define CP_WAIT1()  asm volatile("cp.async.wait_group 1;" ::: "memory")
__device__ __forceinline__ void ldm_x4(uint32_t* r, uint32_t addr) {
    asm volatile("ldmatrix.sync.aligned.m8n8.x4.shared.b16 {%0,%1,%2,%3}, [%4];"
                 : "=r"(r[0]), "=r"(r[1]), "=r"(r[2]), "=r"(r[3]) : "r"(addr));
}
__device__ __forceinline__ void mma_tf32(float* c, const uint32_t* a, const uint32_t* b) {
    asm volatile(
        "mma.sync.aligned.m16n8k8.row.col.f32.tf32.tf32.f32 "
        "{%0,%1,%2,%3}, {%4,%5,%6,%7}, {%8,%9}, {%0,%1,%2,%3};"
        : "+f"(c[0]), "+f"(c[1]), "+f"(c[2]), "+f"(c[3])
        : "r"(a[0]), "r"(a[1]), "r"(a[2]), "r"(a[3]), "r"(b[0]), "r"(b[1]));
}
__device__ __forceinline__ void mma_f16(float* c, const uint32_t* a, const uint32_t* b) {
    asm volatile(
        "mma.sync.aligned.m16n8k16.row.col.f32.f16.f16.f32 "
        "{%0,%1,%2,%3}, {%4,%5,%6,%7}, {%8,%9}, {%0,%1,%2,%3};"
        : "+f"(c[0]), "+f"(c[1]), "+f"(c[2]), "+f"(c[3])
        : "r"(a[0]), "r"(a[1]), "r"(a[2]), "r"(a[3]), "r"(b[0]), "r"(b[1]));
}
__device__ __forceinline__ void h8f(const uint4& r, float* f) {
    const __half2* h = (const __half2*)&r;
#pragma unroll
    for (int i = 0; i < 4; i++) {
        float2 t = __half22float2(h[i]);
        f[i * 2] = t.x; f[i * 2 + 1] = t.y;
    }
}

// ---------------- xpos table init ------------------------------------------
__global__ void xpos_table_kernel(float2* __restrict__ tab) {
    int idx = blockIdx.x * blockDim.x + threadIdx.x;
    if (idx >= 2 * Sq * 64) return;
    int i = idx & 63;
    int pos = (idx >> 6) & (Sq - 1);
    int region = idx >> 17;
    float fi = (float)i;
    float lsb = log2f((fi + 51.2f) * (1.f / 179.2f));
    if (region == 1) lsb = -lsb;
    float pp = (float)pos;
    float sc = exp2f(lsb * pp * (1.f / 512.f));
    float invf = exp2f(fi * (-0.20761871093296528f));
    float s_, c_;
    sincosf(pp * invf, &s_, &c_);
    tab[idx] = make_float2(c_ * sc, s_ * sc);
}

// == fp16 NT GEMM: 128 threads, 4 warps of 64x64, cp.async 3-stage + ldmatrix ==
#define STG 10240
#define GEMM_SMEM (6*STG)
__global__ __launch_bounds__(128, 2) void h_gemm_kernel(
    const __half* __restrict__ A, const __half* __restrict__ Bt,
    float* __restrict__ C, __half* __restrict__ Ch,
    int K, int lda, int ldb, int ldc,
    long aStride, long bStride, long cStride,
    const float* __restrict__ bias, const float* __restrict__ res, int act)
{
    extern __shared__ char hsm[];
    uint32_t sA = smem_u32(hsm);
    uint32_t sB = sA + 3 * STG;
    int z = blockIdx.z;
    A  += z * aStride;
    Bt += z * bStride;
    if (C)  C  += z * cStride;
    if (Ch) Ch += z * cStride;
    if (res) res += z * cStride;
    int bm = blockIdx.y * 128, bn = blockIdx.x * 128;
    int tid = threadIdx.x;
    int lane = tid & 31, warp = tid >> 5;
    int gid = lane >> 2, tig = lane & 3;
    int wy = warp >> 1, wx = warp & 1;   // 2x2 warps, 64x64 each

    float acc[4][8][4];
#pragma unroll
    for (int i = 0; i < 4; i++)
#pragma unroll
        for (int j = 0; j < 8; j++)
#pragma unroll
            for (int k = 0; k < 4; k++) acc[i][j][k] = 0.f;

    uint32_t dBase = sA + tid * (PH * 2);   // one full 32-half row per thread

    int tIn = lane & 7, quad = lane >> 3;
    uint32_t aoff[4], boff[4];
#pragma unroll
    for (int mi = 0; mi < 4; mi++)
        aoff[mi] = sA + 2 * ((wy * 64 + mi * 16 + tIn + (quad & 1) * 8) * PH + (quad >> 1) * 8);
#pragma unroll
    for (int p2 = 0; p2 < 4; p2++)
        boff[p2] = sB + 2 * ((wx * 64 + p2 * 16 + tIn + (quad >> 1) * 8) * PH + (quad & 1) * 8);

#define COPY(s, k0)                                                            \
    {                                                                          \
        uint32_t d = dBase + (s) * STG;                                        \
        const __half* ap = A + (long)(bm + tid) * lda + (k0);                  \
        cp16(d, ap); cp16(d + 16, ap + 8);                                     \
        cp16(d + 32, ap + 16); cp16(d + 48, ap + 24);                          \
        const __half* bp = Bt + (long)(bn + tid) * ldb + (k0);                 \
        cp16(d + 3 * STG, bp); cp16(d + 3 * STG + 16, bp + 8);                 \
        cp16(d + 3 * STG + 32, bp + 16); cp16(d + 3 * STG + 48, bp + 24);      \
    }

#define HCOMP(p)                                                               \
    _Pragma("unroll")                                                          \
    for (int ks = 0; ks < 2; ks++) {                                           \
        uint32_t soff = (p) * STG + ks * 32;                                   \
        uint32_t af[4][4], bq[4][4];                                           \
        _Pragma("unroll")                                                      \
        for (int mi = 0; mi < 4; mi++) ldm_x4(af[mi], aoff[mi] + soff);        \
        _Pragma("unroll")                                                      \
        for (int p2 = 0; p2 < 4; p2++) ldm_x4(bq[p2], boff[p2] + soff);        \
        _Pragma("unroll")                                                      \
        for (int mi = 0; mi < 4; mi++)                                         \
            _Pragma("unroll")                                                  \
            for (int p2 = 0; p2 < 4; p2++) {                                   \
                mma_f16(acc[mi][p2 * 2],     af[mi], &bq[p2][0]);              \
                mma_f16(acc[mi][p2 * 2 + 1], af[mi], &bq[p2][2]);              \
            }                                                                  \
    }

    int nch = K / 32;
    COPY(0, 0)
    CP_COMMIT();
    if (nch > 1) COPY(1, 32)
    CP_COMMIT();
    int st = 0;
    for (int i = 0; i < nch; i++) {
        CP_WAIT1();
        __syncthreads();
        HCOMP(st)
        if (i + 2 < nch) {
            int s2 = st + 2;
            if (s2 >= 3) s2 -= 3;
            COPY(s2, (i + 2) * 32)
        }
        CP_COMMIT();
        if (++st == 3) st = 0;
    }

    // epilogue
#pragma unroll
    for (int mi = 0; mi < 4; mi++) {
        long r0 = bm + wy * 64 + mi * 16 + gid;
        long r1 = r0 + 8;
#pragma unroll
        for (int ni = 0; ni < 8; ni++) {
            int c0 = bn + wx * 64 + ni * 8 + tig * 2;
            float v00 = acc[mi][ni][0], v01 = acc[mi][ni][1];
            float v10 = acc[mi][ni][2], v11 = acc[mi][ni][3];
            if (bias) {
                float b0 = bias[c0], b1 = bias[c0 + 1];
                v00 += b0; v01 += b1; v10 += b0; v11 += b1;
            }
            if (act == 1) {
                v00 = 0.5f * v00 * (1.f + erff(v00 * 0.70710678118654752f));
                v01 = 0.5f * v01 * (1.f + erff(v01 * 0.70710678118654752f));
                v10 = 0.5f * v10 * (1.f + erff(v10 * 0.70710678118654752f));
                v11 = 0.5f * v11 * (1.f + erff(v11 * 0.70710678118654752f));
            } else if (act == 4) {
                int region = c0 >> 9;
                if (region < 2) {
                    int i64 = (c0 & 127) >> 1;
                    long tb = (long)region * Sq * 64 + i64;
                    float2 cs0 = g_xposT[tb + (r0 & (Sq - 1)) * 64];
                    float2 cs1 = g_xposT[tb + (r1 & (Sq - 1)) * 64];
                    float t0 = v00 * cs0.x - v01 * cs0.y;
                    v01 = v01 * cs0.x + v00 * cs0.y;
                    v00 = t0;
                    float t1 = v10 * cs1.x - v11 * cs1.y;
                    v11 = v11 * cs1.x + v10 * cs1.y;
                    v10 = t1;
                }
            }
            if (res) {
                v00 += res[r0 * ldc + c0]; v01 += res[r0 * ldc + c0 + 1];
                v10 += res[r1 * ldc + c0]; v11 += res[r1 * ldc + c0 + 1];
            }
            if (C) {
                *(float2*)(C + r0 * ldc + c0) = make_float2(v00, v01);
                *(float2*)(C + r1 * ldc + c0) = make_float2(v10, v11);
            }
            if (Ch) {
                *(__half2*)(Ch + r0 * ldc + c0) = __floats2half2_rn(v00, v01);
                *(__half2*)(Ch + r1 * ldc + c0) = __floats2half2_rn(v10, v11);
            }
        }
    }
#undef COPY
#undef HCOMP
}

// ---------- pack WQ/WK/WV heads into Wcat rows (transposed, fp16) ----------
__global__ __launch_bounds__(256) void packqkv_kernel(const float* __restrict__ WQ,
                                                      const float* __restrict__ WK,
                                                      const float* __restrict__ WV,
                                                      __half* __restrict__ Wcat) {
    __shared__ float t[32][33];
    int z = blockIdx.z;
    int l = z >> 2, n = z & 3;
    long inOff = (long)z * Hq * HDq;
    int bx = blockIdx.x * 32, by = blockIdx.y * 32;
    int tx = threadIdx.x & 31, ty = threadIdx.x >> 5;
    const float* srcs[3] = {WQ + inOff, WK + inOff, WV + inOff};
    int rowBases[3] = {n * HDq, KOFF + n * HDq, VOFF + n * HDq};
#pragma unroll 1
    for (int m = 0; m < 3; m++) {
        const float* in = srcs[m];
        __syncthreads();
#pragma unroll
        for (int i = 0; i < 32; i += 8)
            t[ty + i][tx] = in[(long)(by + ty + i) * HDq + bx + tx];
        __syncthreads();
        __half* outp = Wcat + ((long)l * QS + rowBases[m] + bx) * Hq + by;
#pragma unroll
        for (int i = 0; i < 32; i += 8)
            outp[(long)(ty + i) * Hq + tx] = __float2half(t[tx][ty + i]);
    }
}

__global__ __launch_bounds__(256) void transposeh_kernel(const float* __restrict__ in,
                                                         __half* __restrict__ out, int R, int C,
                                                         long inZ, long outZ) {
    __shared__ float t[32][33];
    long z = blockIdx.z;
    in  += z * inZ;
    out += z * outZ;
    int bx = blockIdx.x * 32, by = blockIdx.y * 32;
    int tx = threadIdx.x & 31, ty = threadIdx.x >> 5;
#pragma unroll
    for (int i = 0; i < 32; i += 8)
        t[ty + i][tx] = in[(long)(by + ty + i) * C + bx + tx];
    __syncthreads();
#pragma unroll
    for (int i = 0; i < 32; i += 8)
        out[(long)(bx + ty + i) * R + by + tx] = __float2half(t[tx][ty + i]);
}

// ---------------- warp-per-row LayerNorm over H=512, fp16 out ---------------
__global__ __launch_bounds__(256) void ln_kernel(const float* __restrict__ X,
                                                 const float* __restrict__ w,
                                                 const float* __restrict__ b,
                                                 __half* __restrict__ out) {
    int warp = threadIdx.x >> 5, lane = threadIdx.x & 31;
    long row = (long)blockIdx.x * 8 + warp;
    const float* x = X + row * Hq;
    float4 v[4];
#pragma unroll
    for (int i = 0; i < 4; i++) v[i] = *(const float4*)(x + i * 128 + lane * 4);
    float s = 0.f;
#pragma unroll
    for (int i = 0; i < 4; i++) s += v[i].x + v[i].y + v[i].z + v[i].w;
#pragma unroll
    for (int o = 16; o; o >>= 1) s += __shfl_xor_sync(0xffffffffu, s, o);
    float m = s * (1.f / Hq);
    float s2 = 0.f;
#pragma unroll
    for (int i = 0; i < 4; i++) {
        v[i].x -= m; v[i].y -= m; v[i].z -= m; v[i].w -= m;
        s2 += v[i].x * v[i].x + v[i].y * v[i].y + v[i].z * v[i].z + v[i].w * v[i].w;
    }
#pragma unroll
    for (int o = 16; o; o >>= 1) s2 += __shfl_xor_sync(0xffffffffu, s2, o);
    float inv = rsqrtf(s2 * (1.f / Hq) + EPSq);
#pragma unroll
    for (int i = 0; i < 4; i++) {
        int d = i * 128 + lane * 4;
        float4 ww = *(const float4*)(w + d);
        float4 bb = *(const float4*)(b + d);
        *(__half2*)(out + row * Hq + d)     = __floats2half2_rn(v[i].x * inv * ww.x + bb.x, v[i].y * inv * ww.y + bb.y);
        *(__half2*)(out + row * Hq + d + 2) = __floats2half2_rn(v[i].z * inv * ww.z + bb.z, v[i].w * inv * ww.w + bb.w);
    }
}

// ------------- retention pass A: per-chunk decayed KV (fp16 in, tf32 mma) --
__global__ __launch_bounds__(256) void chunk_kv_kernel(const __half* __restrict__ QKVG,
                                                       float* __restrict__ Mout) {
    __shared__ uint32_t KT[128 * PA];
    __shared__ uint32_t VT[128 * PA];
    int bid = blockIdx.x;
    int bn = bid / NCq, c = bid % NCq;
    int b = bn >> 2, n = bn & 3;
    float lgam = logf(gamma_of(n));
    const __half* base = QKVG + ((long)(b * Sq + c * CHq)) * QS;
    const __half* Kb = base + KOFF + n * HDq;
    const __half* Vb = base + VOFF + n * HDq;
    int tid = threadIdx.x;
    int lane = tid & 31, warp = tid >> 5;
    int gid = lane >> 2, tig = lane & 3;
    int wy = warp >> 2, wx = warp & 3;
    float acc[4][4][4];
#pragma unroll
    for (int i = 0; i < 4; i++)
#pragma unroll
        for (int j = 0; j < 4; j++)
#pragma unroll
            for (int k = 0; k < 4; k++) acc[i][j][k] = 0.f;
    int jj = tid >> 4, dbase = (tid & 15) * 8;
    int jjs = jj ^ (tid & 15);
    for (int j0 = 0; j0 < CHq; j0 += 16) {
        int j = j0 + jj;
        float w = expf((float)(127 - j) * lgam);
        uint4 kr = *(const uint4*)(Kb + (long)j * QS + dbase);
        uint4 vr = *(const uint4*)(Vb + (long)j * QS + dbase);
        float kf[8], vf[8];
        h8f(kr, kf); h8f(vr, vf);
        __syncthreads();
#pragma unroll
        for (int i = 0; i < 8; i++) {
            KT[(dbase + i) * PA + jjs] = f2tf(kf[i] * w);
            VT[(dbase + i) * PA + jjs] = f2tf(vf[i]);
        }
        __syncthreads();
#pragma unroll
        for (int kk = 0; kk < 16; kk += 8) {
            uint32_t af[4][4], bf[4][2];
#pragma unroll
            for (int mi = 0; mi < 4; mi++) {
                int m = wy * 64 + mi * 16 + gid;
                int sw = m >> 3, sw2 = (m + 8) >> 3;
                af[mi][0] = KT[m * PA + ((kk + tig) ^ sw)];
                af[mi][1] = KT[(m + 8) * PA + ((kk + tig) ^ sw2)];
                af[mi][2] = KT[m * PA + ((kk + tig + 4) ^ sw)];
                af[mi][3] = KT[(m + 8) * PA + ((kk + tig + 4) ^ sw2)];
            }
#pragma unroll
            for (int ni = 0; ni < 4; ni++) {
                int nb = wx * 32 + ni * 8 + gid;
                int sw = nb >> 3;
                bf[ni][0] = VT[nb * PA + ((kk + tig) ^ sw)];
                bf[ni][1] = VT[nb * PA + ((kk + tig + 4) ^ sw)];
            }
#pragma unroll
            for (int mi = 0; mi < 4; mi++)
#pragma unroll
                for (int ni = 0; ni < 4; ni++)
                    mma_tf32(acc[mi][ni], af[mi], bf[ni]);
        }
    }
    float* Mo = Mout + (long)bid * (HDq * HDq);
#pragma unroll
    for (int mi = 0; mi < 4; mi++) {
        int r0 = wy * 64 + mi * 16 + gid, r1 = r0 + 8;
#pragma unroll
        for (int ni = 0; ni < 4; ni++) {
            int c0 = wx * 32 + ni * 8 + tig * 2;
            *(float2*)(Mo + r0 * HDq + c0) = make_float2(acc[mi][ni][0], acc[mi][ni][1]);
            *(float2*)(Mo + r1 * HDq + c0) = make_float2(acc[mi][ni][2], acc[mi][ni][3]);
        }
    }
}

__global__ __launch_bounds__(256) void scan_kernel(const float* __restrict__ M,
                                                   float* __restrict__ St) {
    long idx = (long)blockIdx.x * blockDim.x + threadIdx.x;
    int bn = (int)(idx >> 14);
    int n = bn & 3;
    float gamma = gamma_of(n);
    float gC = expf(128.f * logf(gamma));
    long e = idx & 16383;
    float s = 0.f;
    for (int c = 0; c < NCq; c++) {
        long off = ((long)bn * NCq + c) * 16384 + e;
        St[off] = s;
        s = s * gC + M[off];
    }
}

// ------- retention pass C: chunk output + fused group-norm + swish gate ----
__global__ __launch_bounds__(256) void chunk_out_kernel(const __half* __restrict__ QKVG,
                                                        const float* __restrict__ States,
                                                        const float* __restrict__ gnw,
                                                        const float* __restrict__ gnb,
                                                        __half* __restrict__ outG) {
    extern __shared__ uint32_t dsm[];
    uint32_t* Asm = dsm;
    uint32_t* T1  = dsm + 128 * PAsm;
    uint32_t* T2  = T1 + 128 * PA;
    int bid = blockIdx.x;
    int bn = bid / NCq, c = bid % NCq;
    int b = bn >> 2, n = bn & 3;
    float lgam = logf(gamma_of(n));
    const __half* base = QKVG + ((long)(b * Sq + c * CHq)) * QS;
    const __half* Qb = base + n * HDq;
    const __half* Kb = base + KOFF + n * HDq;
    const __half* Vb = base + VOFF + n * HDq;
    const float* Sb = States + ((long)bn * NCq + c) * 16384;
    int tid = threadIdx.x;
    int lane = tid & 31, warp = tid >> 5;
    int gid = lane >> 2, tig = lane & 3;
    int wy = warp >> 2, wx = warp & 3;
    float acc[4][4][4];
#pragma unroll
    for (int i = 0; i < 4; i++)
#pragma unroll
        for (int j = 0; j < 4; j++)
#pragma unroll
            for (int k = 0; k < 4; k++) acc[i][j][k] = 0.f;
    int lr = tid >> 1, lc = (tid & 1) * 8;
    int jj = tid >> 4, dbase = (tid & 15) * 8;
    int jjs = jj ^ (tid & 15);

    // phase 1: scores = Q K^T
    for (int d0 = 0; d0 < HDq; d0 += 16) {
        uint4 qr = *(const uint4*)(Qb + (long)lr * QS + d0 + lc);
        uint4 kr = *(const uint4*)(Kb + (long)lr * QS + d0 + lc);
        float qf[8], kf[8];
        h8f(qr, qf); h8f(kr, kf);
        __syncthreads();
        *(uint4*)&T1[lr * PA + lc]     = make_uint4(f2tf(qf[0]), f2tf(qf[1]), f2tf(qf[2]), f2tf(qf[3]));
        *(uint4*)&T1[lr * PA + lc + 4] = make_uint4(f2tf(qf[4]), f2tf(qf[5]), f2tf(qf[6]), f2tf(qf[7]));
        *(uint4*)&T2[lr * PA + lc]     = make_uint4(f2tf(kf[0]), f2tf(kf[1]), f2tf(kf[2]), f2tf(kf[3]));
        *(uint4*)&T2[lr * PA + lc + 4] = make_uint4(f2tf(kf[4]), f2tf(kf[5]), f2tf(kf[6]), f2tf(kf[7]));
        __syncthreads();
#pragma unroll
        for (int kk = 0; kk < 16; kk += 8) {
            uint32_t af[4][4], bf[4][2];
#pragma unroll
            for (int mi = 0; mi < 4; mi++) {
                int mb = (wy * 64 + mi * 16 + gid) * PA + kk + tig;
                af[mi][0] = T1[mb]; af[mi][1] = T1[mb + 8 * PA];
                af[mi][2] = T1[mb + 4]; af[mi][3] = T1[mb + 8 * PA + 4];
            }
#pragma unroll
            for (int ni = 0; ni < 4; ni++) {
                int nb = (wx * 32 + ni * 8 + gid) * PA + kk + tig;
                bf[ni][0] = T2[nb]; bf[ni][1] = T2[nb + 4];
            }
#pragma unroll
            for (int mi = 0; mi < 4; mi++)
#pragma unroll
                for (int ni = 0; ni < 4; ni++)
                    mma_tf32(acc[mi][ni], af[mi], bf[ni]);
        }
    }
    {
        float pj[8], pk[8];
#pragma unroll
        for (int mi = 0; mi < 4; mi++) {
            int r0 = wy * 64 + mi * 16 + gid;
            pj[mi * 2]     = expf((float)r0 * lgam);
            pj[mi * 2 + 1] = expf((float)(r0 + 8) * lgam);
        }
#pragma unroll
        for (int ni = 0; ni < 4; ni++) {
            int c0 = wx * 32 + ni * 8 + tig * 2;
            pk[ni * 2]     = expf((float)(-c0) * lgam);
            pk[ni * 2 + 1] = expf((float)(-(c0 + 1)) * lgam);
        }
        __syncthreads();
#pragma unroll
        for (int mi = 0; mi < 4; mi++) {
            int r0 = wy * 64 + mi * 16 + gid, r1 = r0 + 8;
#pragma unroll
            for (int ni = 0; ni < 4; ni++) {
                int c0 = wx * 32 + ni * 8 + tig * 2;
                float v00 = (r0 >= c0)     ? acc[mi][ni][0] * pj[mi*2]   * pk[ni*2]   : 0.f;
                float v01 = (r0 >= c0 + 1) ? acc[mi][ni][1] * pj[mi*2]   * pk[ni*2+1] : 0.f;
                float v10 = (r1 >= c0)     ? acc[mi][ni][2] * pj[mi*2+1] * pk[ni*2]   : 0.f;
                float v11 = (r1 >= c0 + 1) ? acc[mi][ni][3] * pj[mi*2+1] * pk[ni*2+1] : 0.f;
                Asm[r0 * PAsm + c0]     = f2tf(v00);
                Asm[r0 * PAsm + c0 + 1] = f2tf(v01);
                Asm[r1 * PAsm + c0]     = f2tf(v10);
                Asm[r1 * PAsm + c0 + 1] = f2tf(v11);
                acc[mi][ni][0] = acc[mi][ni][1] = acc[mi][ni][2] = acc[mi][ni][3] = 0.f;
            }
        }
    }
    __syncthreads();

    // phase 2: Y = scores * V
    for (int j0 = 0; j0 < CHq; j0 += 16) {
        uint4 vr = *(const uint4*)(Vb + (long)(j0 + jj) * QS + dbase);
        float vf[8];
        h8f(vr, vf);
        __syncthreads();
#pragma unroll
        for (int i = 0; i < 8; i++)
            T2[(dbase + i) * PA + jjs] = f2tf(vf[i]);
        __syncthreads();
#pragma unroll
        for (int kk = 0; kk < 16; kk += 8) {
            uint32_t af[4][4], bf[4][2];
#pragma unroll
            for (int mi = 0; mi < 4; mi++) {
                int mb = (wy * 64 + mi * 16 + gid) * PAsm + j0 + kk + tig;
                af[mi][0] = Asm[mb]; af[mi][1] = Asm[mb + 8 * PAsm];
                af[mi][2] = Asm[mb + 4]; af[mi][3] = Asm[mb + 8 * PAsm + 4];
            }
#pragma unroll
            for (int ni = 0; ni < 4; ni++) {
                int nb = wx * 32 + ni * 8 + gid;
                int sw = nb >> 3;
                bf[ni][0] = T2[nb * PA + ((kk + tig) ^ sw)];
                bf[ni][1] = T2[nb * PA + ((kk + tig + 4) ^ sw)];
            }
#pragma unroll
            for (int mi = 0; mi < 4; mi++)
#pragma unroll
                for (int ni = 0; ni < 4; ni++)
                    mma_tf32(acc[mi][ni], af[mi], bf[ni]);
        }
    }

    // phase 3: Y += diag(gamma^{j+1}) Q * State
    {
        float wrow = expf((float)(lr + 1) * lgam);
        for (int e0 = 0; e0 < HDq; e0 += 16) {
            uint4 qr = *(const uint4*)(Qb + (long)lr * QS + e0 + lc);
            float qf[8];
            h8f(qr, qf);
            const float* sp = Sb + (long)(e0 + jj) * HDq + dbase;
            float4 s0 = *(const float4*)(sp), s1 = *(const float4*)(sp + 4);
            __syncthreads();
            *(uint4*)&T1[lr * PA + lc]     = make_uint4(f2tf(qf[0] * wrow), f2tf(qf[1] * wrow), f2tf(qf[2] * wrow), f2tf(qf[3] * wrow));
            *(uint4*)&T1[lr * PA + lc + 4] = make_uint4(f2tf(qf[4] * wrow), f2tf(qf[5] * wrow), f2tf(qf[6] * wrow), f2tf(qf[7] * wrow));
            T2[(dbase + 0) * PA + jjs] = f2tf(s0.x);
            T2[(dbase + 1) * PA + jjs] = f2tf(s0.y);
            T2[(dbase + 2) * PA + jjs] = f2tf(s0.z);
            T2[(dbase + 3) * PA + jjs] = f2tf(s0.w);
            T2[(dbase + 4) * PA + jjs] = f2tf(s1.x);
            T2[(dbase + 5) * PA + jjs] = f2tf(s1.y);
            T2[(dbase + 6) * PA + jjs] = f2tf(s1.z);
            T2[(dbase + 7) * PA + jjs] = f2tf(s1.w);
            __syncthreads();
#pragma unroll
            for (int kk = 0; kk < 16; kk += 8) {
                uint32_t af[4][4], bf[4][2];
#pragma unroll
                for (int mi = 0; mi < 4; mi++) {
                    int mb = (wy * 64 + mi * 16 + gid) * PA + kk + tig;
                    af[mi][0] = T1[mb]; af[mi][1] = T1[mb + 8 * PA];
                    af[mi][2] = T1[mb + 4]; af[mi][3] = T1[mb + 8 * PA + 4];
                }
#pragma unroll
                for (int ni = 0; ni < 4; ni++) {
                    int nb = wx * 32 + ni * 8 + gid;
                    int sw = nb >> 3;
                    bf[ni][0] = T2[nb * PA + ((kk + tig) ^ sw)];
                    bf[ni][1] = T2[nb * PA + ((kk + tig + 4) ^ sw)];
                }
#pragma unroll
                for (int mi = 0; mi < 4; mi++)
#pragma unroll
                    for (int ni = 0; ni < 4; ni++)
                        mma_tf32(acc[mi][ni], af[mi], bf[ni]);
            }
        }
    }

    // ---- fused group-norm + swish gate (fp16 out) ----
    float* Ysm = (float*)dsm;
#pragma unroll
    for (int mi = 0; mi < 4; mi++) {
        int r0 = wy * 64 + mi * 16 + gid, r1 = r0 + 8;
#pragma unroll
        for (int ni = 0; ni < 4; ni++) {
            int c0 = wx * 32 + ni * 8 + tig * 2;
            Ysm[r0 * PAsm + c0]     = acc[mi][ni][0];
            Ysm[r0 * PAsm + c0 + 1] = acc[mi][ni][1];
            Ysm[r1 * PAsm + c0]     = acc[mi][ni][2];
            Ysm[r1 * PAsm + c0 + 1] = acc[mi][ni][3];
        }
    }
    __syncthreads();
    const float* gnwh = gnw + n * HDq;
    const float* gnbh = gnb + n * HDq;
#pragma unroll 1
    for (int rr = 0; rr < 16; rr++) {
        int row = warp * 16 + rr;
        float y[4];
#pragma unroll
        for (int i = 0; i < 4; i++) y[i] = Ysm[row * PAsm + lane + 32 * i];
        float s = y[0] + y[1] + y[2] + y[3];
#pragma unroll
        for (int o = 16; o; o >>= 1) s += __shfl_xor_sync(0xffffffffu, s, o);
        float m = s * (1.f / HDq);
        float s2 = 0.f;
#pragma unroll
        for (int i = 0; i < 4; i++) { y[i] -= m; s2 += y[i] * y[i]; }
#pragma unroll
        for (int o = 16; o; o >>= 1) s2 += __shfl_xor_sync(0xffffffffu, s2, o);
        float inv = rsqrtf(s2 * (1.f / HDq) + EPSq);
        long srow = (long)b * Sq + c * CHq + row;
        const __half* gp = QKVG + srow * QS + GOFF + n * HDq;
        __half* op = outG + srow * Hq + n * HDq;
#pragma unroll
        for (int i = 0; i < 4; i++) {
            int d = lane + 32 * i;
            float g = __half2float(gp[d]);
            float yn = y[i] * inv * gnwh[d] + gnbh[d];
            op[d] = __float2half((g / (1.f + expf(-g))) * yn);
        }
    }
}

// ============================================================================
extern "C" void kernel_launch(void* const* d_in, const int* in_sizes, int n_in,
                              void* d_out, int out_size) {
    const float* Xin  = (const float*)d_in[0];
    const float* WQ   = (const float*)d_in[1];
    const float* WK   = (const float*)d_in[2];
    const float* WV   = (const float*)d_in[3];
    const float* WG   = (const float*)d_in[4];
    const float* WO   = (const float*)d_in[5];
    const float* gn_w = (const float*)d_in[6];
    const float* gn_b = (const float*)d_in[7];
    const float* ln1w = (const float*)d_in[8];
    const float* ln1b = (const float*)d_in[9];
    const float* ln2w = (const float*)d_in[10];
    const float* ln2b = (const float*)d_in[11];
    const float* fw1  = (const float*)d_in[12];
    const float* fb1  = (const float*)d_in[13];
    const float* fw2  = (const float*)d_in[14];
    const float* fb2  = (const float*)d_in[15];
    float* out = (float*)d_out;

    float *pY, *pX, *pM, *pSt;
    float2* pXpos;
    __half *pQKVGh, *pXnH, *pGatedH, *pHnH, *pHfH, *pXH;
    __half *pWcat, *pWOTh, *pW1Th, *pW2Th;
    cudaGetSymbolAddress((void**)&pQKVGh, g_QKVGh);
    cudaGetSymbolAddress((void**)&pY, g_Y);
    cudaGetSymbolAddress((void**)&pX, g_X);
    cudaGetSymbolAddress((void**)&pM, g_M);
    cudaGetSymbolAddress((void**)&pSt, g_St);
    cudaGetSymbolAddress((void**)&pXpos, g_xposT);
    cudaGetSymbolAddress((void**)&pXnH, g_XnH);
    cudaGetSymbolAddress((void**)&pGatedH, g_GatedH);
    cudaGetSymbolAddress((void**)&pHnH, g_HnH);
    cudaGetSymbolAddress((void**)&pHfH, g_HfH);
    cudaGetSymbolAddress((void**)&pXH, g_XH);
    cudaGetSymbolAddress((void**)&pWcat, g_Wcat);
    cudaGetSymbolAddress((void**)&pWOTh, g_WOTh);
    cudaGetSymbolAddress((void**)&pW1Th, g_W1Th);
    cudaGetSymbolAddress((void**)&pW2Th, g_W2Th);

    const int smemCO = (128 * PAsm + 2 * 128 * PA) * 4;
    cudaFuncSetAttribute(chunk_out_kernel, cudaFuncAttributeMaxDynamicSharedMemorySize, smemCO);
    cudaFuncSetAttribute(h_gemm_kernel, cudaFuncAttributeMaxDynamicSharedMemorySize, GEMM_SMEM);

    xpos_table_kernel<<<(2 * Sq * 64 + 255) / 256, 256>>>(pXpos);
    packqkv_kernel<<<dim3(4, 16, 12), 256>>>(WQ, WK, WV, pWcat);
    transposeh_kernel<<<dim3(16, 16, 3), 256>>>(WG, pWcat + (long)GOFF * Hq, Hq, Hq,
        (long)Hq * Hq, (long)QS * Hq);
    transposeh_kernel<<<dim3(16, 16, 3), 256>>>(WO, pWOTh, Hq, Hq, (long)Hq * Hq, (long)Hq * Hq);
    transposeh_kernel<<<dim3(64, 16, 3), 256>>>(fw1, pW1Th, Hq, FFNq, (long)Hq * FFNq, (long)Hq * FFNq);
    transposeh_kernel<<<dim3(16, 64, 3), 256>>>(fw2, pW2Th, FFNq, Hq, (long)Hq * FFNq, (long)Hq * FFNq);

    const float* cur = Xin;
    for (int l = 0; l < Lq; l++) {
        ln_kernel<<<BSq / 8, 256>>>(cur, ln1w + (long)l * Hq, ln1b + (long)l * Hq, pXnH);
        h_gemm_kernel<<<dim3(QS / 128, BSq / 128, 1), 128, GEMM_SMEM>>>(
            pXnH, pWcat + (long)l * QS * Hq, nullptr, pQKVGh,
            Hq, Hq, Hq, QS, 0, 0, 0, nullptr, nullptr, 4);
        chunk_kv_kernel<<<Bq * NHq * NCq, 256>>>(pQKVGh, pM);
        scan_kernel<<<(Bq * NHq * HDq * HDq) / 256, 256>>>(pM, pSt);
        chunk_out_kernel<<<Bq * NHq * NCq, 256, smemCO>>>(pQKVGh, pSt,
            gn_w + (long)l * Hq, gn_b + (long)l * Hq, pGatedH);
        h_gemm_kernel<<<dim3(Hq / 128, BSq / 128, 1), 128, GEMM_SMEM>>>(
            pGatedH, pWOTh + (long)l * Hq * Hq, pY, nullptr,
            Hq, Hq, Hq, Hq, 0, 0, 0, nullptr, cur, 0);
        ln_kernel<<<BSq / 8, 256>>>(pY, ln2w + (long)l * Hq, ln2b + (long)l * Hq, pHnH);
        h_gemm_kernel<<<dim3(FFNq / 128, BSq / 128, 1), 128, GEMM_SMEM>>>(
            pHnH, pW1Th + (long)l * Hq * FFNq, nullptr, pHfH,
            Hq, Hq, Hq, FFNq, 0, 0, 0, fb1 + (long)l * FFNq, nullptr, 1);
        float* dst = (l == Lq - 1) ? out : pX;
        __half* dstH = (l == Lq - 1) ? pXH : nullptr;
        h_gemm_kernel<<<dim3(Hq / 128, BSq / 128, 1), 128, GEMM_SMEM>>>(
            pHfH, pW2Th + (long)l * Hq * FFNq, dst, dstH,
            FFNq, FFNq, FFNq, Hq, 0, 0, 0, fb2 + (long)l * Hq, pY, 0);
        cur = dst;
    }

    long nX = (long)BSq * Hq;
    h_gemm_kernel<<<dim3(Sq / 128, Sq / 128, Bq), 128, GEMM_SMEM>>>(
        pXH, pXH, out + nX, nullptr,
        Hq, Hq, Hq, Sq,
        (long)Sq * Hq, (long)Sq * Hq, (long)Sq * Sq,
        nullptr, nullptr, 0);
}

// round 15
// speedup vs baseline: 1.3275x; 1.3275x over previous
#include <cuda_runtime.h>
#include <cuda_fp16.h>
#include <math.h>
#include <stdint.h>

#define Bq   4
#define Sq   2048
#define Hq   512
#define NHq  4
#define HDq  128
#define FFNq 2048
#define Lq   3
#define BSq  (Bq*Sq)
#define CHq  128
#define NCq  (Sq/CHq)
#define EPSq 1e-5f
#define PA   20
#define PAsm 132
#define PH   40
#define QS   2048
#define KOFF 512
#define VOFF 1024
#define GOFF 1536

// fp32 buffers
__device__ float g_Y[BSq*Hq];
__device__ float g_X[BSq*Hq];
__device__ float g_M[Bq*NHq*NCq*HDq*HDq];
__device__ float g_St[Bq*NHq*NCq*HDq*HDq];
__device__ float2 g_xposT[2*Sq*64];
// fp16 buffers
__device__ __half g_QKVGh[BSq*QS];
__device__ __half g_XnH[BSq*Hq];
__device__ __half g_GatedH[BSq*Hq];
__device__ __half g_HnH[BSq*Hq];
__device__ __half g_HfH[BSq*FFNq];
__device__ __half g_XH[BSq*Hq];
// fp16 weights [N][K]
__device__ __half g_Wcat[Lq*QS*Hq];
__device__ __half g_WOTh[Lq*Hq*Hq];
__device__ __half g_W1Th[Lq*FFNq*Hq];
__device__ __half g_W2Th[Lq*Hq*FFNq];

__device__ __forceinline__ float gamma_of(int n) {
    double lg = -3.4657359027997265 + (double)n * (-0.9241962407465937);
    return (float)(1.0 - exp(lg));
}
__device__ __forceinline__ uint32_t f2tf(float x) {
    uint32_t y;
    asm("cvt.rna.tf32.f32 %0, %1;" : "=r"(y) : "f"(x));
    return y;
}
__device__ __forceinline__ uint32_t smem_u32(const void* p) {
    uint32_t a;
    asm("{ .reg .u64 t; cvta.to.shared.u64 t, %1; cvt.u32.u64 %0, t; }" : "=r"(a) : "l"(p));
    return a;
}
__device__ __forceinline__ void cp16(uint32_t saddr, const void* g) {
    asm volatile("cp.async.cg.shared.global [%0], [%1], 16;" :: "r"(saddr), "l"(g));
}
#define CP_COMMIT() asm volatile("cp.async.commit_group;" ::: "memory")
#define CP_WAIT1()  asm volatile("cp.async.wait_group 1;" ::: "memory")
__device__ __forceinline__ void ldm_x4(uint32_t* r, uint32_t addr) {
    asm volatile("ldmatrix.sync.aligned.m8n8.x4.shared.b16 {%0,%1,%2,%3}, [%4];"
                 : "=r"(r[0]), "=r"(r[1]), "=r"(r[2]), "=r"(r[3]) : "r"(addr));
}
__device__ __forceinline__ void mma_tf32(float* c, const uint32_t* a, const uint32_t* b) {
    asm volatile(
        "mma.sync.aligned.m16n8k8.row.col.f32.tf32.tf32.f32 "
        "{%0,%1,%2,%3}, {%4,%5,%6,%7}, {%8,%9}, {%0,%1,%2,%3};"
        : "+f"(c[0]), "+f"(c[1]), "+f"(c[2]), "+f"(c[3])
        : "r"(a[0]), "r"(a[1]), "r"(a[2]), "r"(a[3]), "r"(b[0]), "r"(b[1]));
}
__device__ __forceinline__ void mma_f16(float* c, const uint32_t* a, const uint32_t* b) {
    asm volatile(
        "mma.sync.aligned.m16n8k16.row.col.f32.f16.f16.f32 "
        "{%0,%1,%2,%3}, {%4,%5,%6,%7}, {%8,%9}, {%0,%1,%2,%3};"
        : "+f"(c[0]), "+f"(c[1]), "+f"(c[2]), "+f"(c[3])
        : "r"(a[0]), "r"(a[1]), "r"(a[2]), "r"(a[3]), "r"(b[0]), "r"(b[1]));
}
__device__ __forceinline__ void h8f(const uint4& r, float* f) {
    const __half2* h = (const __half2*)&r;
#pragma unroll
    for (int i = 0; i < 4; i++) {
        float2 t = __half22float2(h[i]);
        f[i * 2] = t.x; f[i * 2 + 1] = t.y;
    }
}

// ---------------- xpos table init ------------------------------------------
__global__ void xpos_table_kernel(float2* __restrict__ tab) {
    int idx = blockIdx.x * blockDim.x + threadIdx.x;
    if (idx >= 2 * Sq * 64) return;
    int i = idx & 63;
    int pos = (idx >> 6) & (Sq - 1);
    int region = idx >> 17;
    float fi = (float)i;
    float lsb = log2f((fi + 51.2f) * (1.f / 179.2f));
    if (region == 1) lsb = -lsb;
    float pp = (float)pos;
    float sc = exp2f(lsb * pp * (1.f / 512.f));
    float invf = exp2f(fi * (-0.20761871093296528f));
    float s_, c_;
    sincosf(pp * invf, &s_, &c_);
    tab[idx] = make_float2(c_ * sc, s_ * sc);
}

// ====== fp16 NT GEMM: cp.async 3-stage pipeline + ldmatrix fragments =======
#define STG 10240
#define GEMM_SMEM (6*STG)
__global__ __launch_bounds__(256, 2) void h_gemm_kernel(
    const __half* __restrict__ A, const __half* __restrict__ Bt,
    float* __restrict__ C, __half* __restrict__ Ch,
    int K, int lda, int ldb, int ldc,
    long aStride, long bStride, long cStride,
    const float* __restrict__ bias, const float* __restrict__ res, int act)
{
    extern __shared__ char hsm[];
    uint32_t sA = smem_u32(hsm);
    uint32_t sB = sA + 3 * STG;
    int z = blockIdx.z;
    A  += z * aStride;
    Bt += z * bStride;
    if (C)  C  += z * cStride;
    if (Ch) Ch += z * cStride;
    if (res) res += z * cStride;
    int bm = blockIdx.y * 128, bn = blockIdx.x * 128;
    int tid = threadIdx.x;
    int lane = tid & 31, warp = tid >> 5;
    int gid = lane >> 2, tig = lane & 3;
    int wy = warp >> 2, wx = warp & 3;

    float acc[4][4][4];
#pragma unroll
    for (int i = 0; i < 4; i++)
#pragma unroll
        for (int j = 0; j < 4; j++)
#pragma unroll
            for (int k = 0; k < 4; k++) acc[i][j][k] = 0.f;

    int lr = tid >> 1, lkh = (tid & 1) * 16;
    uint32_t dBase = sA + (lr * PH + lkh) * 2;

    int tIn = lane & 7, quad = lane >> 3;
    uint32_t aoff[4], boff[2];
#pragma unroll
    for (int mi = 0; mi < 4; mi++)
        aoff[mi] = sA + 2 * ((wy * 64 + mi * 16 + tIn + (quad & 1) * 8) * PH + (quad >> 1) * 8);
#pragma unroll
    for (int p2 = 0; p2 < 2; p2++)
        boff[p2] = sB + 2 * ((wx * 32 + p2 * 16 + tIn + (quad >> 1) * 8) * PH + (quad & 1) * 8);

#define COPY(s, k0)                                                            \
    {                                                                          \
        uint32_t d = dBase + (s) * STG;                                        \
        const __half* ap = A + (long)(bm + lr) * lda + (k0) + lkh;             \
        cp16(d, ap); cp16(d + 16, ap + 8);                                     \
        const __half* bp = Bt + (long)(bn + lr) * ldb + (k0) + lkh;            \
        cp16(d + 3 * STG, bp); cp16(d + 3 * STG + 16, bp + 8);                 \
    }

#define HCOMP(p)                                                               \
    _Pragma("unroll")                                                          \
    for (int ks = 0; ks < 2; ks++) {                                           \
        uint32_t soff = (p) * STG + ks * 32;                                   \
        uint32_t af[4][4], bq[2][4];                                           \
        _Pragma("unroll")                                                      \
        for (int mi = 0; mi < 4; mi++) ldm_x4(af[mi], aoff[mi] + soff);        \
        ldm_x4(bq[0], boff[0] + soff);                                         \
        ldm_x4(bq[1], boff[1] + soff);                                         \
        _Pragma("unroll")                                                      \
        for (int mi = 0; mi < 4; mi++) {                                       \
            mma_f16(acc[mi][0], af[mi], &bq[0][0]);                            \
            mma_f16(acc[mi][1], af[mi], &bq[0][2]);                            \
            mma_f16(acc[mi][2], af[mi], &bq[1][0]);                            \
            mma_f16(acc[mi][3], af[mi], &bq[1][2]);                            \
        }                                                                      \
    }

    int nch = K / 32;
    COPY(0, 0)
    CP_COMMIT();
    if (nch > 1) COPY(1, 32)
    CP_COMMIT();
    int st = 0;
    for (int i = 0; i < nch; i++) {
        CP_WAIT1();
        __syncthreads();
        HCOMP(st)
        if (i + 2 < nch) {
            int s2 = st + 2;
            if (s2 >= 3) s2 -= 3;
            COPY(s2, (i + 2) * 32)
        }
        CP_COMMIT();
        if (++st == 3) st = 0;
    }

    // epilogue
#pragma unroll
    for (int mi = 0; mi < 4; mi++) {
        long r0 = bm + wy * 64 + mi * 16 + gid;
        long r1 = r0 + 8;
#pragma unroll
        for (int ni = 0; ni < 4; ni++) {
            int c0 = bn + wx * 32 + ni * 8 + tig * 2;
            float v00 = acc[mi][ni][0], v01 = acc[mi][ni][1];
            float v10 = acc[mi][ni][2], v11 = acc[mi][ni][3];
            if (bias) {
                float b0 = bias[c0], b1 = bias[c0 + 1];
                v00 += b0; v01 += b1; v10 += b0; v11 += b1;
            }
            if (act == 1) {
                v00 = 0.5f * v00 * (1.f + erff(v00 * 0.70710678118654752f));
                v01 = 0.5f * v01 * (1.f + erff(v01 * 0.70710678118654752f));
                v10 = 0.5f * v10 * (1.f + erff(v10 * 0.70710678118654752f));
                v11 = 0.5f * v11 * (1.f + erff(v11 * 0.70710678118654752f));
            } else if (act == 4) {
                int region = c0 >> 9;
                if (region < 2) {
                    int i64 = (c0 & 127) >> 1;
                    long tb = (long)region * Sq * 64 + i64;
                    float2 cs0 = g_xposT[tb + (r0 & (Sq - 1)) * 64];
                    float2 cs1 = g_xposT[tb + (r1 & (Sq - 1)) * 64];
                    float t0 = v00 * cs0.x - v01 * cs0.y;
                    v01 = v01 * cs0.x + v00 * cs0.y;
                    v00 = t0;
                    float t1 = v10 * cs1.x - v11 * cs1.y;
                    v11 = v11 * cs1.x + v10 * cs1.y;
                    v10 = t1;
                }
            }
            if (res) {
                v00 += res[r0 * ldc + c0]; v01 += res[r0 * ldc + c0 + 1];
                v10 += res[r1 * ldc + c0]; v11 += res[r1 * ldc + c0 + 1];
            }
            if (C) {
                *(float2*)(C + r0 * ldc + c0) = make_float2(v00, v01);
                *(float2*)(C + r1 * ldc + c0) = make_float2(v10, v11);
            }
            if (Ch) {
                *(__half2*)(Ch + r0 * ldc + c0) = __floats2half2_rn(v00, v01);
                *(__half2*)(Ch + r1 * ldc + c0) = __floats2half2_rn(v10, v11);
            }
        }
    }
#undef COPY
#undef HCOMP
}

// ---------- pack WQ/WK/WV heads into Wcat rows (transposed, fp16) ----------
__global__ __launch_bounds__(256) void packqkv_kernel(const float* __restrict__ WQ,
                                                      const float* __restrict__ WK,
                                                      const float* __restrict__ WV,
                                                      __half* __restrict__ Wcat) {
    __shared__ float t[32][33];
    int z = blockIdx.z;
    int l = z >> 2, n = z & 3;
    long inOff = (long)z * Hq * HDq;
    int bx = blockIdx.x * 32, by = blockIdx.y * 32;
    int tx = threadIdx.x & 31, ty = threadIdx.x >> 5;
    const float* srcs[3] = {WQ + inOff, WK + inOff, WV + inOff};
    int rowBases[3] = {n * HDq, KOFF + n * HDq, VOFF + n * HDq};
#pragma unroll 1
    for (int m = 0; m < 3; m++) {
        const float* in = srcs[m];
        __syncthreads();
#pragma unroll
        for (int i = 0; i < 32; i += 8)
            t[ty + i][tx] = in[(long)(by + ty + i) * HDq + bx + tx];
        __syncthreads();
        __half* outp = Wcat + ((long)l * QS + rowBases[m] + bx) * Hq + by;
#pragma unroll
        for (int i = 0; i < 32; i += 8)
            outp[(long)(ty + i) * Hq + tx] = __float2half(t[tx][ty + i]);
    }
}

__global__ __launch_bounds__(256) void transposeh_kernel(const float* __restrict__ in,
                                                         __half* __restrict__ out, int R, int C,
                                                         long inZ, long outZ) {
    __shared__ float t[32][33];
    long z = blockIdx.z;
    in  += z * inZ;
    out += z * outZ;
    int bx = blockIdx.x * 32, by = blockIdx.y * 32;
    int tx = threadIdx.x & 31, ty = threadIdx.x >> 5;
#pragma unroll
    for (int i = 0; i < 32; i += 8)
        t[ty + i][tx] = in[(long)(by + ty + i) * C + bx + tx];
    __syncthreads();
#pragma unroll
    for (int i = 0; i < 32; i += 8)
        out[(long)(bx + ty + i) * R + by + tx] = __float2half(t[tx][ty + i]);
}

// ---------------- warp-per-row LayerNorm over H=512, fp16 out ---------------
__global__ __launch_bounds__(256) void ln_kernel(const float* __restrict__ X,
                                                 const float* __restrict__ w,
                                                 const float* __restrict__ b,
                                                 __half* __restrict__ out) {
    int warp = threadIdx.x >> 5, lane = threadIdx.x & 31;
    long row = (long)blockIdx.x * 8 + warp;
    const float* x = X + row * Hq;
    float4 v[4];
#pragma unroll
    for (int i = 0; i < 4; i++) v[i] = *(const float4*)(x + i * 128 + lane * 4);
    float s = 0.f;
#pragma unroll
    for (int i = 0; i < 4; i++) s += v[i].x + v[i].y + v[i].z + v[i].w;
#pragma unroll
    for (int o = 16; o; o >>= 1) s += __shfl_xor_sync(0xffffffffu, s, o);
    float m = s * (1.f / Hq);
    float s2 = 0.f;
#pragma unroll
    for (int i = 0; i < 4; i++) {
        v[i].x -= m; v[i].y -= m; v[i].z -= m; v[i].w -= m;
        s2 += v[i].x * v[i].x + v[i].y * v[i].y + v[i].z * v[i].z + v[i].w * v[i].w;
    }
#pragma unroll
    for (int o = 16; o; o >>= 1) s2 += __shfl_xor_sync(0xffffffffu, s2, o);
    float inv = rsqrtf(s2 * (1.f / Hq) + EPSq);
#pragma unroll
    for (int i = 0; i < 4; i++) {
        int d = i * 128 + lane * 4;
        float4 ww = *(const float4*)(w + d);
        float4 bb = *(const float4*)(b + d);
        *(__half2*)(out + row * Hq + d)     = __floats2half2_rn(v[i].x * inv * ww.x + bb.x, v[i].y * inv * ww.y + bb.y);
        *(__half2*)(out + row * Hq + d + 2) = __floats2half2_rn(v[i].z * inv * ww.z + bb.z, v[i].w * inv * ww.w + bb.w);
    }
}

// ------------- retention pass A: per-chunk decayed KV (fp16 in, tf32 mma) --
__global__ __launch_bounds__(256) void chunk_kv_kernel(const __half* __restrict__ QKVG,
                                                       float* __restrict__ Mout) {
    __shared__ uint32_t KT[128 * PA];
    __shared__ uint32_t VT[128 * PA];
    int bid = blockIdx.x;
    int bn = bid / NCq, c = bid % NCq;
    int b = bn >> 2, n = bn & 3;
    float lgam = logf(gamma_of(n));
    const __half* base = QKVG + ((long)(b * Sq + c * CHq)) * QS;
    const __half* Kb = base + KOFF + n * HDq;
    const __half* Vb = base + VOFF + n * HDq;
    int tid = threadIdx.x;
    int lane = tid & 31, warp = tid >> 5;
    int gid = lane >> 2, tig = lane & 3;
    int wy = warp >> 2, wx = warp & 3;
    float acc[4][4][4];
#pragma unroll
    for (int i = 0; i < 4; i++)
#pragma unroll
        for (int j = 0; j < 4; j++)
#pragma unroll
            for (int k = 0; k < 4; k++) acc[i][j][k] = 0.f;
    int jj = tid >> 4, dbase = (tid & 15) * 8;
    int jjs = jj ^ (tid & 15);
    for (int j0 = 0; j0 < CHq; j0 += 16) {
        int j = j0 + jj;
        float w = expf((float)(127 - j) * lgam);
        uint4 kr = *(const uint4*)(Kb + (long)j * QS + dbase);
        uint4 vr = *(const uint4*)(Vb + (long)j * QS + dbase);
        float kf[8], vf[8];
        h8f(kr, kf); h8f(vr, vf);
        __syncthreads();
#pragma unroll
        for (int i = 0; i < 8; i++) {
            KT[(dbase + i) * PA + jjs] = f2tf(kf[i] * w);
            VT[(dbase + i) * PA + jjs] = f2tf(vf[i]);
        }
        __syncthreads();
#pragma unroll
        for (int kk = 0; kk < 16; kk += 8) {
            uint32_t af[4][4], bf[4][2];
#pragma unroll
            for (int mi = 0; mi < 4; mi++) {
                int m = wy * 64 + mi * 16 + gid;
                int sw = m >> 3, sw2 = (m + 8) >> 3;
                af[mi][0] = KT[m * PA + ((kk + tig) ^ sw)];
                af[mi][1] = KT[(m + 8) * PA + ((kk + tig) ^ sw2)];
                af[mi][2] = KT[m * PA + ((kk + tig + 4) ^ sw)];
                af[mi][3] = KT[(m + 8) * PA + ((kk + tig + 4) ^ sw2)];
            }
#pragma unroll
            for (int ni = 0; ni < 4; ni++) {
                int nb = wx * 32 + ni * 8 + gid;
                int sw = nb >> 3;
                bf[ni][0] = VT[nb * PA + ((kk + tig) ^ sw)];
                bf[ni][1] = VT[nb * PA + ((kk + tig + 4) ^ sw)];
            }
#pragma unroll
            for (int mi = 0; mi < 4; mi++)
#pragma unroll
                for (int ni = 0; ni < 4; ni++)
                    mma_tf32(acc[mi][ni], af[mi], bf[ni]);
        }
    }
    float* Mo = Mout + (long)bid * (HDq * HDq);
#pragma unroll
    for (int mi = 0; mi < 4; mi++) {
        int r0 = wy * 64 + mi * 16 + gid, r1 = r0 + 8;
#pragma unroll
        for (int ni = 0; ni < 4; ni++) {
            int c0 = wx * 32 + ni * 8 + tig * 2;
            *(float2*)(Mo + r0 * HDq + c0) = make_float2(acc[mi][ni][0], acc[mi][ni][1]);
            *(float2*)(Mo + r1 * HDq + c0) = make_float2(acc[mi][ni][2], acc[mi][ni][3]);
        }
    }
}

__global__ __launch_bounds__(256) void scan_kernel(const float* __restrict__ M,
                                                   float* __restrict__ St) {
    long idx = (long)blockIdx.x * blockDim.x + threadIdx.x;
    int bn = (int)(idx >> 14);
    int n = bn & 3;
    float gamma = gamma_of(n);
    float gC = expf(128.f * logf(gamma));
    long e = idx & 16383;
    float s = 0.f;
    for (int c = 0; c < NCq; c++) {
        long off = ((long)bn * NCq + c) * 16384 + e;
        St[off] = s;
        s = s * gC + M[off];
    }
}

// ------- retention pass C: chunk output + fused group-norm + swish gate ----
__global__ __launch_bounds__(256) void chunk_out_kernel(const __half* __restrict__ QKVG,
                                                        const float* __restrict__ States,
                                                        const float* __restrict__ gnw,
                                                        const float* __restrict__ gnb,
                                                        __half* __restrict__ outG) {
    extern __shared__ uint32_t dsm[];
    uint32_t* Asm = dsm;
    uint32_t* T1  = dsm + 128 * PAsm;
    uint32_t* T2  = T1 + 128 * PA;
    int bid = blockIdx.x;
    int bn = bid / NCq, c = bid % NCq;
    int b = bn >> 2, n = bn & 3;
    float lgam = logf(gamma_of(n));
    const __half* base = QKVG + ((long)(b * Sq + c * CHq)) * QS;
    const __half* Qb = base + n * HDq;
    const __half* Kb = base + KOFF + n * HDq;
    const __half* Vb = base + VOFF + n * HDq;
    const float* Sb = States + ((long)bn * NCq + c) * 16384;
    int tid = threadIdx.x;
    int lane = tid & 31, warp = tid >> 5;
    int gid = lane >> 2, tig = lane & 3;
    int wy = warp >> 2, wx = warp & 3;
    float acc[4][4][4];
#pragma unroll
    for (int i = 0; i < 4; i++)
#pragma unroll
        for (int j = 0; j < 4; j++)
#pragma unroll
            for (int k = 0; k < 4; k++) acc[i][j][k] = 0.f;
    int lr = tid >> 1, lc = (tid & 1) * 8;
    int jj = tid >> 4, dbase = (tid & 15) * 8;
    int jjs = jj ^ (tid & 15);

    // phase 1: scores = Q K^T
    for (int d0 = 0; d0 < HDq; d0 += 16) {
        uint4 qr = *(const uint4*)(Qb + (long)lr * QS + d0 + lc);
        uint4 kr = *(const uint4*)(Kb + (long)lr * QS + d0 + lc);
        float qf[8], kf[8];
        h8f(qr, qf); h8f(kr, kf);
        __syncthreads();
        *(uint4*)&T1[lr * PA + lc]     = make_uint4(f2tf(qf[0]), f2tf(qf[1]), f2tf(qf[2]), f2tf(qf[3]));
        *(uint4*)&T1[lr * PA + lc + 4] = make_uint4(f2tf(qf[4]), f2tf(qf[5]), f2tf(qf[6]), f2tf(qf[7]));
        *(uint4*)&T2[lr * PA + lc]     = make_uint4(f2tf(kf[0]), f2tf(kf[1]), f2tf(kf[2]), f2tf(kf[3]));
        *(uint4*)&T2[lr * PA + lc + 4] = make_uint4(f2tf(kf[4]), f2tf(kf[5]), f2tf(kf[6]), f2tf(kf[7]));
        __syncthreads();
#pragma unroll
        for (int kk = 0; kk < 16; kk += 8) {
            uint32_t af[4][4], bf[4][2];
#pragma unroll
            for (int mi = 0; mi < 4; mi++) {
                int mb = (wy * 64 + mi * 16 + gid) * PA + kk + tig;
                af[mi][0] = T1[mb]; af[mi][1] = T1[mb + 8 * PA];
                af[mi][2] = T1[mb + 4]; af[mi][3] = T1[mb + 8 * PA + 4];
            }
#pragma unroll
            for (int ni = 0; ni < 4; ni++) {
                int nb = (wx * 32 + ni * 8 + gid) * PA + kk + tig;
                bf[ni][0] = T2[nb]; bf[ni][1] = T2[nb + 4];
            }
#pragma unroll
            for (int mi = 0; mi < 4; mi++)
#pragma unroll
                for (int ni = 0; ni < 4; ni++)
                    mma_tf32(acc[mi][ni], af[mi], bf[ni]);
        }
    }
    {
        float pj[8], pk[8];
#pragma unroll
        for (int mi = 0; mi < 4; mi++) {
            int r0 = wy * 64 + mi * 16 + gid;
            pj[mi * 2]     = expf((float)r0 * lgam);
            pj[mi * 2 + 1] = expf((float)(r0 + 8) * lgam);
        }
#pragma unroll
        for (int ni = 0; ni < 4; ni++) {
            int c0 = wx * 32 + ni * 8 + tig * 2;
            pk[ni * 2]     = expf((float)(-c0) * lgam);
            pk[ni * 2 + 1] = expf((float)(-(c0 + 1)) * lgam);
        }
        __syncthreads();
#pragma unroll
        for (int mi = 0; mi < 4; mi++) {
            int r0 = wy * 64 + mi * 16 + gid, r1 = r0 + 8;
#pragma unroll
            for (int ni = 0; ni < 4; ni++) {
                int c0 = wx * 32 + ni * 8 + tig * 2;
                float v00 = (r0 >= c0)     ? acc[mi][ni][0] * pj[mi*2]   * pk[ni*2]   : 0.f;
                float v01 = (r0 >= c0 + 1) ? acc[mi][ni][1] * pj[mi*2]   * pk[ni*2+1] : 0.f;
                float v10 = (r1 >= c0)     ? acc[mi][ni][2] * pj[mi*2+1] * pk[ni*2]   : 0.f;
                float v11 = (r1 >= c0 + 1) ? acc[mi][ni][3] * pj[mi*2+1] * pk[ni*2+1] : 0.f;
                Asm[r0 * PAsm + c0]     = f2tf(v00);
                Asm[r0 * PAsm + c0 + 1] = f2tf(v01);
                Asm[r1 * PAsm + c0]     = f2tf(v10);
                Asm[r1 * PAsm + c0 + 1] = f2tf(v11);
                acc[mi][ni][0] = acc[mi][ni][1] = acc[mi][ni][2] = acc[mi][ni][3] = 0.f;
            }
        }
    }
    __syncthreads();

    // phase 2: Y = scores * V
    for (int j0 = 0; j0 < CHq; j0 += 16) {
        uint4 vr = *(const uint4*)(Vb + (long)(j0 + jj) * QS + dbase);
        float vf[8];
        h8f(vr, vf);
        __syncthreads();
#pragma unroll
        for (int i = 0; i < 8; i++)
            T2[(dbase + i) * PA + jjs] = f2tf(vf[i]);
        __syncthreads();
#pragma unroll
        for (int kk = 0; kk < 16; kk += 8) {
            uint32_t af[4][4], bf[4][2];
#pragma unroll
            for (int mi = 0; mi < 4; mi++) {
                int mb = (wy * 64 + mi * 16 + gid) * PAsm + j0 + kk + tig;
                af[mi][0] = Asm[mb]; af[mi][1] = Asm[mb + 8 * PAsm];
                af[mi][2] = Asm[mb + 4]; af[mi][3] = Asm[mb + 8 * PAsm + 4];
            }
#pragma unroll
            for (int ni = 0; ni < 4; ni++) {
                int nb = wx * 32 + ni * 8 + gid;
                int sw = nb >> 3;
                bf[ni][0] = T2[nb * PA + ((kk + tig) ^ sw)];
                bf[ni][1] = T2[nb * PA + ((kk + tig + 4) ^ sw)];
            }
#pragma unroll
            for (int mi = 0; mi < 4; mi++)
#pragma unroll
                for (int ni = 0; ni < 4; ni++)
                    mma_tf32(acc[mi][ni], af[mi], bf[ni]);
        }
    }

    // phase 3: Y += diag(gamma^{j+1}) Q * State
    {
        float wrow = expf((float)(lr + 1) * lgam);
        for (int e0 = 0; e0 < HDq; e0 += 16) {
            uint4 qr = *(const uint4*)(Qb + (long)lr * QS + e0 + lc);
            float qf[8];
            h8f(qr, qf);
            const float* sp = Sb + (long)(e0 + jj) * HDq + dbase;
            float4 s0 = *(const float4*)(sp), s1 = *(const float4*)(sp + 4);
            __syncthreads();
            *(uint4*)&T1[lr * PA + lc]     = make_uint4(f2tf(qf[0] * wrow), f2tf(qf[1] * wrow), f2tf(qf[2] * wrow), f2tf(qf[3] * wrow));
            *(uint4*)&T1[lr * PA + lc + 4] = make_uint4(f2tf(qf[4] * wrow), f2tf(qf[5] * wrow), f2tf(qf[6] * wrow), f2tf(qf[7] * wrow));
            T2[(dbase + 0) * PA + jjs] = f2tf(s0.x);
            T2[(dbase + 1) * PA + jjs] = f2tf(s0.y);
            T2[(dbase + 2) * PA + jjs] = f2tf(s0.z);
            T2[(dbase + 3) * PA + jjs] = f2tf(s0.w);
            T2[(dbase + 4) * PA + jjs] = f2tf(s1.x);
            T2[(dbase + 5) * PA + jjs] = f2tf(s1.y);
            T2[(dbase + 6) * PA + jjs] = f2tf(s1.z);
            T2[(dbase + 7) * PA + jjs] = f2tf(s1.w);
            __syncthreads();
#pragma unroll
            for (int kk = 0; kk < 16; kk += 8) {
                uint32_t af[4][4], bf[4][2];
#pragma unroll
                for (int mi = 0; mi < 4; mi++) {
                    int mb = (wy * 64 + mi * 16 + gid) * PA + kk + tig;
                    af[mi][0] = T1[mb]; af[mi][1] = T1[mb + 8 * PA];
                    af[mi][2] = T1[mb + 4]; af[mi][3] = T1[mb + 8 * PA + 4];
                }
#pragma unroll
                for (int ni = 0; ni < 4; ni++) {
                    int nb = wx * 32 + ni * 8 + gid;
                    int sw = nb >> 3;
                    bf[ni][0] = T2[nb * PA + ((kk + tig) ^ sw)];
                    bf[ni][1] = T2[nb * PA + ((kk + tig + 4) ^ sw)];
                }
#pragma unroll
                for (int mi = 0; mi < 4; mi++)
#pragma unroll
                    for (int ni = 0; ni < 4; ni++)
                        mma_tf32(acc[mi][ni], af[mi], bf[ni]);
            }
        }
    }

    // ---- fused group-norm + swish gate (fp16 out) ----
    float* Ysm = (float*)dsm;
#pragma unroll
    for (int mi = 0; mi < 4; mi++) {
        int r0 = wy * 64 + mi * 16 + gid, r1 = r0 + 8;
#pragma unroll
        for (int ni = 0; ni < 4; ni++) {
            int c0 = wx * 32 + ni * 8 + tig * 2;
            Ysm[r0 * PAsm + c0]     = acc[mi][ni][0];
            Ysm[r0 * PAsm + c0 + 1] = acc[mi][ni][1];
            Ysm[r1 * PAsm + c0]     = acc[mi][ni][2];
            Ysm[r1 * PAsm + c0 + 1] = acc[mi][ni][3];
        }
    }
    __syncthreads();
    const float* gnwh = gnw + n * HDq;
    const float* gnbh = gnb + n * HDq;
#pragma unroll 1
    for (int rr = 0; rr < 16; rr++) {
        int row = warp * 16 + rr;
        float y[4];
#pragma unroll
        for (int i = 0; i < 4; i++) y[i] = Ysm[row * PAsm + lane + 32 * i];
        float s = y[0] + y[1] + y[2] + y[3];
#pragma unroll
        for (int o = 16; o; o >>= 1) s += __shfl_xor_sync(0xffffffffu, s, o);
        float m = s * (1.f / HDq);
        float s2 = 0.f;
#pragma unroll
        for (int i = 0; i < 4; i++) { y[i] -= m; s2 += y[i] * y[i]; }
#pragma unroll
        for (int o = 16; o; o >>= 1) s2 += __shfl_xor_sync(0xffffffffu, s2, o);
        float inv = rsqrtf(s2 * (1.f / HDq) + EPSq);
        long srow = (long)b * Sq + c * CHq + row;
        const __half* gp = QKVG + srow * QS + GOFF + n * HDq;
        __half* op = outG + srow * Hq + n * HDq;
#pragma unroll
        for (int i = 0; i < 4; i++) {
            int d = lane + 32 * i;
            float g = __half2float(gp[d]);
            float yn = y[i] * inv * gnwh[d] + gnbh[d];
            op[d] = __float2half((g / (1.f + expf(-g))) * yn);
        }
    }
}

// ============================================================================
extern "C" void kernel_launch(void* const* d_in, const int* in_sizes, int n_in,
                              void* d_out, int out_size) {
    const float* Xin  = (const float*)d_in[0];
    const float* WQ   = (const float*)d_in[1];
    const float* WK   = (const float*)d_in[2];
    const float* WV   = (const float*)d_in[3];
    const float* WG   = (const float*)d_in[4];
    const float* WO   = (const float*)d_in[5];
    const float* gn_w = (const float*)d_in[6];
    const float* gn_b = (const float*)d_in[7];
    const float* ln1w = (const float*)d_in[8];
    const float* ln1b = (const float*)d_in[9];
    const float* ln2w = (const float*)d_in[10];
    const float* ln2b = (const float*)d_in[11];
    const float* fw1  = (const float*)d_in[12];
    const float* fb1  = (const float*)d_in[13];
    const float* fw2  = (const float*)d_in[14];
    const float* fb2  = (const float*)d_in[15];
    float* out = (float*)d_out;

    float *pY, *pX, *pM, *pSt;
    float2* pXpos;
    __half *pQKVGh, *pXnH, *pGatedH, *pHnH, *pHfH, *pXH;
    __half *pWcat, *pWOTh, *pW1Th, *pW2Th;
    cudaGetSymbolAddress((void**)&pQKVGh, g_QKVGh);
    cudaGetSymbolAddress((void**)&pY, g_Y);
    cudaGetSymbolAddress((void**)&pX, g_X);
    cudaGetSymbolAddress((void**)&pM, g_M);
    cudaGetSymbolAddress((void**)&pSt, g_St);
    cudaGetSymbolAddress((void**)&pXpos, g_xposT);
    cudaGetSymbolAddress((void**)&pXnH, g_XnH);
    cudaGetSymbolAddress((void**)&pGatedH, g_GatedH);
    cudaGetSymbolAddress((void**)&pHnH, g_HnH);
    cudaGetSymbolAddress((void**)&pHfH, g_HfH);
    cudaGetSymbolAddress((void**)&pXH, g_XH);
    cudaGetSymbolAddress((void**)&pWcat, g_Wcat);
    cudaGetSymbolAddress((void**)&pWOTh, g_WOTh);
    cudaGetSymbolAddress((void**)&pW1Th, g_W1Th);
    cudaGetSymbolAddress((void**)&pW2Th, g_W2Th);

    const int smemCO = (128 * PAsm + 2 * 128 * PA) * 4;
    cudaFuncSetAttribute(chunk_out_kernel, cudaFuncAttributeMaxDynamicSharedMemorySize, smemCO);
    cudaFuncSetAttribute(h_gemm_kernel, cudaFuncAttributeMaxDynamicSharedMemorySize, GEMM_SMEM);

    xpos_table_kernel<<<(2 * Sq * 64 + 255) / 256, 256>>>(pXpos);
    packqkv_kernel<<<dim3(4, 16, 12), 256>>>(WQ, WK, WV, pWcat);
    transposeh_kernel<<<dim3(16, 16, 3), 256>>>(WG, pWcat + (long)GOFF * Hq, Hq, Hq,
        (long)Hq * Hq, (long)QS * Hq);
    transposeh_kernel<<<dim3(16, 16, 3), 256>>>(WO, pWOTh, Hq, Hq, (long)Hq * Hq, (long)Hq * Hq);
    transposeh_kernel<<<dim3(64, 16, 3), 256>>>(fw1, pW1Th, Hq, FFNq, (long)Hq * FFNq, (long)Hq * FFNq);
    transposeh_kernel<<<dim3(16, 64, 3), 256>>>(fw2, pW2Th, FFNq, Hq, (long)Hq * FFNq, (long)Hq * FFNq);

    const float* cur = Xin;
    for (int l = 0; l < Lq; l++) {
        ln_kernel<<<BSq / 8, 256>>>(cur, ln1w + (long)l * Hq, ln1b + (long)l * Hq, pXnH);
        h_gemm_kernel<<<dim3(QS / 128, BSq / 128, 1), 256, GEMM_SMEM>>>(
            pXnH, pWcat + (long)l * QS * Hq, nullptr, pQKVGh,
            Hq, Hq, Hq, QS, 0, 0, 0, nullptr, nullptr, 4);
        chunk_kv_kernel<<<Bq * NHq * NCq, 256>>>(pQKVGh, pM);
        scan_kernel<<<(Bq * NHq * HDq * HDq) / 256, 256>>>(pM, pSt);
        chunk_out_kernel<<<Bq * NHq * NCq, 256, smemCO>>>(pQKVGh, pSt,
            gn_w + (long)l * Hq, gn_b + (long)l * Hq, pGatedH);
        h_gemm_kernel<<<dim3(Hq / 128, BSq / 128, 1), 256, GEMM_SMEM>>>(
            pGatedH, pWOTh + (long)l * Hq * Hq, pY, nullptr,
            Hq, Hq, Hq, Hq, 0, 0, 0, nullptr, cur, 0);
        ln_kernel<<<BSq / 8, 256>>>(pY, ln2w + (long)l * Hq, ln2b + (long)l * Hq, pHnH);
        h_gemm_kernel<<<dim3(FFNq / 128, BSq / 128, 1), 256, GEMM_SMEM>>>(
            pHnH, pW1Th + (long)l * Hq * FFNq, nullptr, pHfH,
            Hq, Hq, Hq, FFNq, 0, 0, 0, fb1 + (long)l * FFNq, nullptr, 1);
        float* dst = (l == Lq - 1) ? out : pX;
        __half* dstH = (l == Lq - 1) ? pXH : nullptr;
        h_gemm_kernel<<<dim3(Hq / 128, BSq / 128, 1), 256, GEMM_SMEM>>>(
            pHfH, pW2Th + (long)l * Hq * FFNq, dst, dstH,
            FFNq, FFNq, FFNq, Hq, 0, 0, 0, fb2 + (long)l * Hq, pY, 0);
        cur = dst;
    }

    long nX = (long)BSq * Hq;
    h_gemm_kernel<<<dim3(Sq / 128, Sq / 128, Bq), 256, GEMM_SMEM>>>(
        pXH, pXH, out + nX, nullptr,
        Hq, Hq, Hq, Sq,
        (long)Sq * Hq, (long)Sq * Hq, (long)Sq * Sq,
        nullptr, nullptr, 0);
}

// round 16
// speedup vs baseline: 1.3454x; 1.0135x over previous
#include <cuda_runtime.h>
#include <cuda_fp16.h>
#include <math.h>
#include <stdint.h>

#define Bq   4
#define Sq   2048
#define Hq   512
#define NHq  4
#define HDq  128
#define FFNq 2048
#define Lq   3
#define BSq  (Bq*Sq)
#define CHq  128
#define NCq  (Sq/CHq)
#define EPSq 1e-5f
#define PA   20
#define PAsm 132
#define PH   40
#define QS   2048
#define KOFF 512
#define VOFF 1024
#define GOFF 1536

// fp32 buffers
__device__ float g_Y[BSq*Hq];
__device__ float g_X[BSq*Hq];
__device__ float g_M[Bq*NHq*NCq*HDq*HDq];
__device__ float g_St[Bq*NHq*NCq*HDq*HDq];
__device__ float2 g_xposT[2*Sq*64];
// fp16 buffers
__device__ __half g_QKVGh[BSq*QS];
__device__ __half g_XnH[BSq*Hq];
__device__ __half g_GatedH[BSq*Hq];
__device__ __half g_HnH[BSq*Hq];
__device__ __half g_HfH[BSq*FFNq];
__device__ __half g_XH[BSq*Hq];
// fp16 weights [N][K]
__device__ __half g_Wcat[Lq*QS*Hq];
__device__ __half g_WOTh[Lq*Hq*Hq];
__device__ __half g_W1Th[Lq*FFNq*Hq];
__device__ __half g_W2Th[Lq*Hq*FFNq];

__device__ __forceinline__ float gamma_of(int n) {
    double lg = -3.4657359027997265 + (double)n * (-0.9241962407465937);
    return (float)(1.0 - exp(lg));
}
__device__ __forceinline__ uint32_t f2tf(float x) {
    uint32_t y;
    asm("cvt.rna.tf32.f32 %0, %1;" : "=r"(y) : "f"(x));
    return y;
}
__device__ __forceinline__ uint32_t smem_u32(const void* p) {
    uint32_t a;
    asm("{ .reg .u64 t; cvta.to.shared.u64 t, %1; cvt.u32.u64 %0, t; }" : "=r"(a) : "l"(p));
    return a;
}
__device__ __forceinline__ void cp16(uint32_t saddr, const void* g) {
    asm volatile("cp.async.cg.shared.global [%0], [%1], 16;" :: "r"(saddr), "l"(g));
}
#define CP_COMMIT() asm volatile("cp.async.commit_group;" ::: "memory")
#define CP_WAIT1()  asm volatile("cp.async.wait_group 1;" ::: "memory")
__device__ __forceinline__ void ldm_x4(uint32_t* r, uint32_t addr) {
    asm volatile("ldmatrix.sync.aligned.m8n8.x4.shared.b16 {%0,%1,%2,%3}, [%4];"
                 : "=r"(r[0]), "=r"(r[1]), "=r"(r[2]), "=r"(r[3]) : "r"(addr));
}
__device__ __forceinline__ void mma_tf32(float* c, const uint32_t* a, const uint32_t* b) {
    asm volatile(
        "mma.sync.aligned.m16n8k8.row.col.f32.tf32.tf32.f32 "
        "{%0,%1,%2,%3}, {%4,%5,%6,%7}, {%8,%9}, {%0,%1,%2,%3};"
        : "+f"(c[0]), "+f"(c[1]), "+f"(c[2]), "+f"(c[3])
        : "r"(a[0]), "r"(a[1]), "r"(a[2]), "r"(a[3]), "r"(b[0]), "r"(b[1]));
}
__device__ __forceinline__ void mma_f16(float* c, const uint32_t* a, const uint32_t* b) {
    asm volatile(
        "mma.sync.aligned.m16n8k16.row.col.f32.f16.f16.f32 "
        "{%0,%1,%2,%3}, {%4,%5,%6,%7}, {%8,%9}, {%0,%1,%2,%3};"
        : "+f"(c[0]), "+f"(c[1]), "+f"(c[2]), "+f"(c[3])
        : "r"(a[0]), "r"(a[1]), "r"(a[2]), "r"(a[3]), "r"(b[0]), "r"(b[1]));
}
__device__ __forceinline__ void h8f(const uint4& r, float* f) {
    const __half2* h = (const __half2*)&r;
#pragma unroll
    for (int i = 0; i < 4; i++) {
        float2 t = __half22float2(h[i]);
        f[i * 2] = t.x; f[i * 2 + 1] = t.y;
    }
}

// ---------------- xpos table init ------------------------------------------
__global__ void xpos_table_kernel(float2* __restrict__ tab) {
    int idx = blockIdx.x * blockDim.x + threadIdx.x;
    if (idx >= 2 * Sq * 64) return;
    int i = idx & 63;
    int pos = (idx >> 6) & (Sq - 1);
    int region = idx >> 17;
    float fi = (float)i;
    float lsb = log2f((fi + 51.2f) * (1.f / 179.2f));
    if (region == 1) lsb = -lsb;
    float pp = (float)pos;
    float sc = exp2f(lsb * pp * (1.f / 512.f));
    float invf = exp2f(fi * (-0.20761871093296528f));
    float s_, c_;
    sincosf(pp * invf, &s_, &c_);
    tab[idx] = make_float2(c_ * sc, s_ * sc);
}

// ====== fp16 NT GEMM: cp.async 3-stage pipeline + ldmatrix fragments =======
// act: 0 none, 1 gelu, 4 fused-QKVG (table xpos), 5 symmetric-output (XXt)
#define STG 10240
#define GEMM_SMEM (6*STG)
__global__ __launch_bounds__(256, 2) void h_gemm_kernel(
    const __half* __restrict__ A, const __half* __restrict__ Bt,
    float* __restrict__ C, __half* __restrict__ Ch,
    int K, int lda, int ldb, int ldc,
    long aStride, long bStride, long cStride,
    const float* __restrict__ bias, const float* __restrict__ res, int act)
{
    extern __shared__ char hsm[];
    uint32_t sA = smem_u32(hsm);
    uint32_t sB = sA + 3 * STG;
    int z = blockIdx.z;
    A  += z * aStride;
    Bt += z * bStride;
    if (C)  C  += z * cStride;
    if (Ch) Ch += z * cStride;
    if (res) res += z * cStride;
    int bm, bn;
    bool mir = false;
    if (act == 5) {
        int t = blockIdx.x;
        int by = (int)((sqrtf(8.f * (float)t + 1.f) - 1.f) * 0.5f);
        while ((by + 1) * (by + 2) / 2 <= t) by++;
        while (by * (by + 1) / 2 > t) by--;
        int bx = t - by * (by + 1) / 2;
        bm = by * 128; bn = bx * 128;
        mir = (by != bx);
    } else {
        bm = blockIdx.y * 128; bn = blockIdx.x * 128;
    }
    int tid = threadIdx.x;
    int lane = tid & 31, warp = tid >> 5;
    int gid = lane >> 2, tig = lane & 3;
    int wy = warp >> 2, wx = warp & 3;

    float acc[4][4][4];
#pragma unroll
    for (int i = 0; i < 4; i++)
#pragma unroll
        for (int j = 0; j < 4; j++)
#pragma unroll
            for (int k = 0; k < 4; k++) acc[i][j][k] = 0.f;

    int lr = tid >> 1, lkh = (tid & 1) * 16;
    uint32_t dBase = sA + (lr * PH + lkh) * 2;

    int tIn = lane & 7, quad = lane >> 3;
    uint32_t aoff[4], boff[2];
#pragma unroll
    for (int mi = 0; mi < 4; mi++)
        aoff[mi] = sA + 2 * ((wy * 64 + mi * 16 + tIn + (quad & 1) * 8) * PH + (quad >> 1) * 8);
#pragma unroll
    for (int p2 = 0; p2 < 2; p2++)
        boff[p2] = sB + 2 * ((wx * 32 + p2 * 16 + tIn + (quad >> 1) * 8) * PH + (quad & 1) * 8);

#define COPY(s, k0)                                                            \
    {                                                                          \
        uint32_t d = dBase + (s) * STG;                                        \
        const __half* ap = A + (long)(bm + lr) * lda + (k0) + lkh;             \
        cp16(d, ap); cp16(d + 16, ap + 8);                                     \
        const __half* bp = Bt + (long)(bn + lr) * ldb + (k0) + lkh;            \
        cp16(d + 3 * STG, bp); cp16(d + 3 * STG + 16, bp + 8);                 \
    }

#define HCOMP(p)                                                               \
    _Pragma("unroll")                                                          \
    for (int ks = 0; ks < 2; ks++) {                                           \
        uint32_t soff = (p) * STG + ks * 32;                                   \
        uint32_t af[4][4], bq[2][4];                                           \
        _Pragma("unroll")                                                      \
        for (int mi = 0; mi < 4; mi++) ldm_x4(af[mi], aoff[mi] + soff);        \
        ldm_x4(bq[0], boff[0] + soff);                                         \
        ldm_x4(bq[1], boff[1] + soff);                                         \
        _Pragma("unroll")                                                      \
        for (int mi = 0; mi < 4; mi++) {                                       \
            mma_f16(acc[mi][0], af[mi], &bq[0][0]);                            \
            mma_f16(acc[mi][1], af[mi], &bq[0][2]);                            \
            mma_f16(acc[mi][2], af[mi], &bq[1][0]);                            \
            mma_f16(acc[mi][3], af[mi], &bq[1][2]);                            \
        }                                                                      \
    }

    int nch = K / 32;
    COPY(0, 0)
    CP_COMMIT();
    if (nch > 1) COPY(1, 32)
    CP_COMMIT();
    int st = 0;
    for (int i = 0; i < nch; i++) {
        CP_WAIT1();
        __syncthreads();
        HCOMP(st)
        if (i + 2 < nch) {
            int s2 = st + 2;
            if (s2 >= 3) s2 -= 3;
            COPY(s2, (i + 2) * 32)
        }
        CP_COMMIT();
        if (++st == 3) st = 0;
    }

    // epilogue
#pragma unroll
    for (int mi = 0; mi < 4; mi++) {
        long r0 = bm + wy * 64 + mi * 16 + gid;
        long r1 = r0 + 8;
#pragma unroll
        for (int ni = 0; ni < 4; ni++) {
            int c0 = bn + wx * 32 + ni * 8 + tig * 2;
            float v00 = acc[mi][ni][0], v01 = acc[mi][ni][1];
            float v10 = acc[mi][ni][2], v11 = acc[mi][ni][3];
            if (bias) {
                float b0 = bias[c0], b1 = bias[c0 + 1];
                v00 += b0; v01 += b1; v10 += b0; v11 += b1;
            }
            if (act == 1) {
                v00 = 0.5f * v00 * (1.f + erff(v00 * 0.70710678118654752f));
                v01 = 0.5f * v01 * (1.f + erff(v01 * 0.70710678118654752f));
                v10 = 0.5f * v10 * (1.f + erff(v10 * 0.70710678118654752f));
                v11 = 0.5f * v11 * (1.f + erff(v11 * 0.70710678118654752f));
            } else if (act == 4) {
                int region = c0 >> 9;
                if (region < 2) {
                    int i64 = (c0 & 127) >> 1;
                    long tb = (long)region * Sq * 64 + i64;
                    float2 cs0 = g_xposT[tb + (r0 & (Sq - 1)) * 64];
                    float2 cs1 = g_xposT[tb + (r1 & (Sq - 1)) * 64];
                    float t0 = v00 * cs0.x - v01 * cs0.y;
                    v01 = v01 * cs0.x + v00 * cs0.y;
                    v00 = t0;
                    float t1 = v10 * cs1.x - v11 * cs1.y;
                    v11 = v11 * cs1.x + v10 * cs1.y;
                    v10 = t1;
                }
            }
            if (res) {
                v00 += res[r0 * ldc + c0]; v01 += res[r0 * ldc + c0 + 1];
                v10 += res[r1 * ldc + c0]; v11 += res[r1 * ldc + c0 + 1];
            }
            if (C) {
                *(float2*)(C + r0 * ldc + c0) = make_float2(v00, v01);
                *(float2*)(C + r1 * ldc + c0) = make_float2(v10, v11);
                if (mir) {
                    C[(long)c0 * ldc + r0]       = v00;
                    C[(long)(c0 + 1) * ldc + r0] = v01;
                    C[(long)c0 * ldc + r1]       = v10;
                    C[(long)(c0 + 1) * ldc + r1] = v11;
                }
            }
            if (Ch) {
                *(__half2*)(Ch + r0 * ldc + c0) = __floats2half2_rn(v00, v01);
                *(__half2*)(Ch + r1 * ldc + c0) = __floats2half2_rn(v10, v11);
            }
        }
    }
#undef COPY
#undef HCOMP
}

// ---------- pack WQ/WK/WV heads into Wcat rows (transposed, fp16) ----------
__global__ __launch_bounds__(256) void packqkv_kernel(const float* __restrict__ WQ,
                                                      const float* __restrict__ WK,
                                                      const float* __restrict__ WV,
                                                      __half* __restrict__ Wcat) {
    __shared__ float t[32][33];
    int z = blockIdx.z;
    int l = z >> 2, n = z & 3;
    long inOff = (long)z * Hq * HDq;
    int bx = blockIdx.x * 32, by = blockIdx.y * 32;
    int tx = threadIdx.x & 31, ty = threadIdx.x >> 5;
    const float* srcs[3] = {WQ + inOff, WK + inOff, WV + inOff};
    int rowBases[3] = {n * HDq, KOFF + n * HDq, VOFF + n * HDq};
#pragma unroll 1
    for (int m = 0; m < 3; m++) {
        const float* in = srcs[m];
        __syncthreads();
#pragma unroll
        for (int i = 0; i < 32; i += 8)
            t[ty + i][tx] = in[(long)(by + ty + i) * HDq + bx + tx];
        __syncthreads();
        __half* outp = Wcat + ((long)l * QS + rowBases[m] + bx) * Hq + by;
#pragma unroll
        for (int i = 0; i < 32; i += 8)
            outp[(long)(ty + i) * Hq + tx] = __float2half(t[tx][ty + i]);
    }
}

__global__ __launch_bounds__(256) void transposeh_kernel(const float* __restrict__ in,
                                                         __half* __restrict__ out, int R, int C,
                                                         long inZ, long outZ) {
    __shared__ float t[32][33];
    long z = blockIdx.z;
    in  += z * inZ;
    out += z * outZ;
    int bx = blockIdx.x * 32, by = blockIdx.y * 32;
    int tx = threadIdx.x & 31, ty = threadIdx.x >> 5;
#pragma unroll
    for (int i = 0; i < 32; i += 8)
        t[ty + i][tx] = in[(long)(by + ty + i) * C + bx + tx];
    __syncthreads();
#pragma unroll
    for (int i = 0; i < 32; i += 8)
        out[(long)(bx + ty + i) * R + by + tx] = __float2half(t[tx][ty + i]);
}

// ---------------- warp-per-row LayerNorm over H=512, fp16 out ---------------
__global__ __launch_bounds__(256) void ln_kernel(const float* __restrict__ X,
                                                 const float* __restrict__ w,
                                                 const float* __restrict__ b,
                                                 __half* __restrict__ out) {
    int warp = threadIdx.x >> 5, lane = threadIdx.x & 31;
    long row = (long)blockIdx.x * 8 + warp;
    const float* x = X + row * Hq;
    float4 v[4];
#pragma unroll
    for (int i = 0; i < 4; i++) v[i] = *(const float4*)(x + i * 128 + lane * 4);
    float s = 0.f;
#pragma unroll
    for (int i = 0; i < 4; i++) s += v[i].x + v[i].y + v[i].z + v[i].w;
#pragma unroll
    for (int o = 16; o; o >>= 1) s += __shfl_xor_sync(0xffffffffu, s, o);
    float m = s * (1.f / Hq);
    float s2 = 0.f;
#pragma unroll
    for (int i = 0; i < 4; i++) {
        v[i].x -= m; v[i].y -= m; v[i].z -= m; v[i].w -= m;
        s2 += v[i].x * v[i].x + v[i].y * v[i].y + v[i].z * v[i].z + v[i].w * v[i].w;
    }
#pragma unroll
    for (int o = 16; o; o >>= 1) s2 += __shfl_xor_sync(0xffffffffu, s2, o);
    float inv = rsqrtf(s2 * (1.f / Hq) + EPSq);
#pragma unroll
    for (int i = 0; i < 4; i++) {
        int d = i * 128 + lane * 4;
        float4 ww = *(const float4*)(w + d);
        float4 bb = *(const float4*)(b + d);
        *(__half2*)(out + row * Hq + d)     = __floats2half2_rn(v[i].x * inv * ww.x + bb.x, v[i].y * inv * ww.y + bb.y);
        *(__half2*)(out + row * Hq + d + 2) = __floats2half2_rn(v[i].z * inv * ww.z + bb.z, v[i].w * inv * ww.w + bb.w);
    }
}

// ------------- retention pass A: per-chunk decayed KV (fp16 in, tf32 mma) --
__global__ __launch_bounds__(256) void chunk_kv_kernel(const __half* __restrict__ QKVG,
                                                       float* __restrict__ Mout) {
    __shared__ uint32_t KT[128 * PA];
    __shared__ uint32_t VT[128 * PA];
    int bid = blockIdx.x;
    int bn = bid / NCq, c = bid % NCq;
    int b = bn >> 2, n = bn & 3;
    float lgam = logf(gamma_of(n));
    const __half* base = QKVG + ((long)(b * Sq + c * CHq)) * QS;
    const __half* Kb = base + KOFF + n * HDq;
    const __half* Vb = base + VOFF + n * HDq;
    int tid = threadIdx.x;
    int lane = tid & 31, warp = tid >> 5;
    int gid = lane >> 2, tig = lane & 3;
    int wy = warp >> 2, wx = warp & 3;
    float acc[4][4][4];
#pragma unroll
    for (int i = 0; i < 4; i++)
#pragma unroll
        for (int j = 0; j < 4; j++)
#pragma unroll
            for (int k = 0; k < 4; k++) acc[i][j][k] = 0.f;
    int jj = tid >> 4, dbase = (tid & 15) * 8;
    int jjs = jj ^ (tid & 15);
    for (int j0 = 0; j0 < CHq; j0 += 16) {
        int j = j0 + jj;
        float w = expf((float)(127 - j) * lgam);
        uint4 kr = *(const uint4*)(Kb + (long)j * QS + dbase);
        uint4 vr = *(const uint4*)(Vb + (long)j * QS + dbase);
        float kf[8], vf[8];
        h8f(kr, kf); h8f(vr, vf);
        __syncthreads();
#pragma unroll
        for (int i = 0; i < 8; i++) {
            KT[(dbase + i) * PA + jjs] = f2tf(kf[i] * w);
            VT[(dbase + i) * PA + jjs] = f2tf(vf[i]);
        }
        __syncthreads();
#pragma unroll
        for (int kk = 0; kk < 16; kk += 8) {
            uint32_t af[4][4], bf[4][2];
#pragma unroll
            for (int mi = 0; mi < 4; mi++) {
                int m = wy * 64 + mi * 16 + gid;
                int sw = m >> 3, sw2 = (m + 8) >> 3;
                af[mi][0] = KT[m * PA + ((kk + tig) ^ sw)];
                af[mi][1] = KT[(m + 8) * PA + ((kk + tig) ^ sw2)];
                af[mi][2] = KT[m * PA + ((kk + tig + 4) ^ sw)];
                af[mi][3] = KT[(m + 8) * PA + ((kk + tig + 4) ^ sw2)];
            }
#pragma unroll
            for (int ni = 0; ni < 4; ni++) {
                int nb = wx * 32 + ni * 8 + gid;
                int sw = nb >> 3;
                bf[ni][0] = VT[nb * PA + ((kk + tig) ^ sw)];
                bf[ni][1] = VT[nb * PA + ((kk + tig + 4) ^ sw)];
            }
#pragma unroll
            for (int mi = 0; mi < 4; mi++)
#pragma unroll
                for (int ni = 0; ni < 4; ni++)
                    mma_tf32(acc[mi][ni], af[mi], bf[ni]);
        }
    }
    float* Mo = Mout + (long)bid * (HDq * HDq);
#pragma unroll
    for (int mi = 0; mi < 4; mi++) {
        int r0 = wy * 64 + mi * 16 + gid, r1 = r0 + 8;
#pragma unroll
        for (int ni = 0; ni < 4; ni++) {
            int c0 = wx * 32 + ni * 8 + tig * 2;
            *(float2*)(Mo + r0 * HDq + c0) = make_float2(acc[mi][ni][0], acc[mi][ni][1]);
            *(float2*)(Mo + r1 * HDq + c0) = make_float2(acc[mi][ni][2], acc[mi][ni][3]);
        }
    }
}

__global__ __launch_bounds__(256) void scan_kernel(const float* __restrict__ M,
                                                   float* __restrict__ St) {
    long idx = (long)blockIdx.x * blockDim.x + threadIdx.x;
    int bn = (int)(idx >> 14);
    int n = bn & 3;
    float gamma = gamma_of(n);
    float gC = expf(128.f * logf(gamma));
    long e = idx & 16383;
    float s = 0.f;
    for (int c = 0; c < NCq; c++) {
        long off = ((long)bn * NCq + c) * 16384 + e;
        St[off] = s;
        s = s * gC + M[off];
    }
}

// ------- retention pass C: chunk output + fused group-norm + swish gate ----
__global__ __launch_bounds__(256) void chunk_out_kernel(const __half* __restrict__ QKVG,
                                                        const float* __restrict__ States,
                                                        const float* __restrict__ gnw,
                                                        const float* __restrict__ gnb,
                                                        __half* __restrict__ outG) {
    extern __shared__ uint32_t dsm[];
    uint32_t* Asm = dsm;
    uint32_t* T1  = dsm + 128 * PAsm;
    uint32_t* T2  = T1 + 128 * PA;
    int bid = blockIdx.x;
    int bn = bid / NCq, c = bid % NCq;
    int b = bn >> 2, n = bn & 3;
    float lgam = logf(gamma_of(n));
    const __half* base = QKVG + ((long)(b * Sq + c * CHq)) * QS;
    const __half* Qb = base + n * HDq;
    const __half* Kb = base + KOFF + n * HDq;
    const __half* Vb = base + VOFF + n * HDq;
    const float* Sb = States + ((long)bn * NCq + c) * 16384;
    int tid = threadIdx.x;
    int lane = tid & 31, warp = tid >> 5;
    int gid = lane >> 2, tig = lane & 3;
    int wy = warp >> 2, wx = warp & 3;
    float acc[4][4][4];
#pragma unroll
    for (int i = 0; i < 4; i++)
#pragma unroll
        for (int j = 0; j < 4; j++)
#pragma unroll
            for (int k = 0; k < 4; k++) acc[i][j][k] = 0.f;
    int lr = tid >> 1, lc = (tid & 1) * 8;
    int jj = tid >> 4, dbase = (tid & 15) * 8;
    int jjs = jj ^ (tid & 15);
    // fully-masked phase-1 warp tile: all rows < all cols
    bool p1skip = (wy * 64 + 63) < (wx * 32);

    // phase 1: scores = Q K^T
    for (int d0 = 0; d0 < HDq; d0 += 16) {
        uint4 qr = *(const uint4*)(Qb + (long)lr * QS + d0 + lc);
        uint4 kr = *(const uint4*)(Kb + (long)lr * QS + d0 + lc);
        float qf[8], kf[8];
        h8f(qr, qf); h8f(kr, kf);
        __syncthreads();
        *(uint4*)&T1[lr * PA + lc]     = make_uint4(f2tf(qf[0]), f2tf(qf[1]), f2tf(qf[2]), f2tf(qf[3]));
        *(uint4*)&T1[lr * PA + lc + 4] = make_uint4(f2tf(qf[4]), f2tf(qf[5]), f2tf(qf[6]), f2tf(qf[7]));
        *(uint4*)&T2[lr * PA + lc]     = make_uint4(f2tf(kf[0]), f2tf(kf[1]), f2tf(kf[2]), f2tf(kf[3]));
        *(uint4*)&T2[lr * PA + lc + 4] = make_uint4(f2tf(kf[4]), f2tf(kf[5]), f2tf(kf[6]), f2tf(kf[7]));
        __syncthreads();
        if (!p1skip) {
#pragma unroll
            for (int kk = 0; kk < 16; kk += 8) {
                uint32_t af[4][4], bf[4][2];
#pragma unroll
                for (int mi = 0; mi < 4; mi++) {
                    int mb = (wy * 64 + mi * 16 + gid) * PA + kk + tig;
                    af[mi][0] = T1[mb]; af[mi][1] = T1[mb + 8 * PA];
                    af[mi][2] = T1[mb + 4]; af[mi][3] = T1[mb + 8 * PA + 4];
                }
#pragma unroll
                for (int ni = 0; ni < 4; ni++) {
                    int nb = (wx * 32 + ni * 8 + gid) * PA + kk + tig;
                    bf[ni][0] = T2[nb]; bf[ni][1] = T2[nb + 4];
                }
#pragma unroll
                for (int mi = 0; mi < 4; mi++)
#pragma unroll
                    for (int ni = 0; ni < 4; ni++)
                        mma_tf32(acc[mi][ni], af[mi], bf[ni]);
            }
        }
    }
    {
        float pj[8], pk[8];
#pragma unroll
        for (int mi = 0; mi < 4; mi++) {
            int r0 = wy * 64 + mi * 16 + gid;
            pj[mi * 2]     = expf((float)r0 * lgam);
            pj[mi * 2 + 1] = expf((float)(r0 + 8) * lgam);
        }
#pragma unroll
        for (int ni = 0; ni < 4; ni++) {
            int c0 = wx * 32 + ni * 8 + tig * 2;
            pk[ni * 2]     = expf((float)(-c0) * lgam);
            pk[ni * 2 + 1] = expf((float)(-(c0 + 1)) * lgam);
        }
        __syncthreads();
#pragma unroll
        for (int mi = 0; mi < 4; mi++) {
            int r0 = wy * 64 + mi * 16 + gid, r1 = r0 + 8;
#pragma unroll
            for (int ni = 0; ni < 4; ni++) {
                int c0 = wx * 32 + ni * 8 + tig * 2;
                float v00 = (r0 >= c0)     ? acc[mi][ni][0] * pj[mi*2]   * pk[ni*2]   : 0.f;
                float v01 = (r0 >= c0 + 1) ? acc[mi][ni][1] * pj[mi*2]   * pk[ni*2+1] : 0.f;
                float v10 = (r1 >= c0)     ? acc[mi][ni][2] * pj[mi*2+1] * pk[ni*2]   : 0.f;
                float v11 = (r1 >= c0 + 1) ? acc[mi][ni][3] * pj[mi*2+1] * pk[ni*2+1] : 0.f;
                Asm[r0 * PAsm + c0]     = f2tf(v00);
                Asm[r0 * PAsm + c0 + 1] = f2tf(v01);
                Asm[r1 * PAsm + c0]     = f2tf(v10);
                Asm[r1 * PAsm + c0 + 1] = f2tf(v11);
                acc[mi][ni][0] = acc[mi][ni][1] = acc[mi][ni][2] = acc[mi][ni][3] = 0.f;
            }
        }
    }
    __syncthreads();

    // phase 2: Y = scores * V  (scores rows < j are zero; wy==0 rows end at 63)
    for (int j0 = 0; j0 < CHq; j0 += 16) {
        uint4 vr = *(const uint4*)(Vb + (long)(j0 + jj) * QS + dbase);
        float vf[8];
        h8f(vr, vf);
        __syncthreads();
#pragma unroll
        for (int i = 0; i < 8; i++)
            T2[(dbase + i) * PA + jjs] = f2tf(vf[i]);
        __syncthreads();
        if (!(wy == 0 && j0 >= 64)) {
#pragma unroll
            for (int kk = 0; kk < 16; kk += 8) {
                uint32_t af[4][4], bf[4][2];
#pragma unroll
                for (int mi = 0; mi < 4; mi++) {
                    int mb = (wy * 64 + mi * 16 + gid) * PAsm + j0 + kk + tig;
                    af[mi][0] = Asm[mb]; af[mi][1] = Asm[mb + 8 * PAsm];
                    af[mi][2] = Asm[mb + 4]; af[mi][3] = Asm[mb + 8 * PAsm + 4];
                }
#pragma unroll
                for (int ni = 0; ni < 4; ni++) {
                    int nb = wx * 32 + ni * 8 + gid;
                    int sw = nb >> 3;
                    bf[ni][0] = T2[nb * PA + ((kk + tig) ^ sw)];
                    bf[ni][1] = T2[nb * PA + ((kk + tig + 4) ^ sw)];
                }
#pragma unroll
                for (int mi = 0; mi < 4; mi++)
#pragma unroll
                    for (int ni = 0; ni < 4; ni++)
                        mma_tf32(acc[mi][ni], af[mi], bf[ni]);
            }
        }
    }

    // phase 3: Y += diag(gamma^{j+1}) Q * State
    {
        float wrow = expf((float)(lr + 1) * lgam);
        for (int e0 = 0; e0 < HDq; e0 += 16) {
            uint4 qr = *(const uint4*)(Qb + (long)lr * QS + e0 + lc);
            float qf[8];
            h8f(qr, qf);
            const float* sp = Sb + (long)(e0 + jj) * HDq + dbase;
            float4 s0 = *(const float4*)(sp), s1 = *(const float4*)(sp + 4);
            __syncthreads();
            *(uint4*)&T1[lr * PA + lc]     = make_uint4(f2tf(qf[0] * wrow), f2tf(qf[1] * wrow), f2tf(qf[2] * wrow), f2tf(qf[3] * wrow));
            *(uint4*)&T1[lr * PA + lc + 4] = make_uint4(f2tf(qf[4] * wrow), f2tf(qf[5] * wrow), f2tf(qf[6] * wrow), f2tf(qf[7] * wrow));
            T2[(dbase + 0) * PA + jjs] = f2tf(s0.x);
            T2[(dbase + 1) * PA + jjs] = f2tf(s0.y);
            T2[(dbase + 2) * PA + jjs] = f2tf(s0.z);
            T2[(dbase + 3) * PA + jjs] = f2tf(s0.w);
            T2[(dbase + 4) * PA + jjs] = f2tf(s1.x);
            T2[(dbase + 5) * PA + jjs] = f2tf(s1.y);
            T2[(dbase + 6) * PA + jjs] = f2tf(s1.z);
            T2[(dbase + 7) * PA + jjs] = f2tf(s1.w);
            __syncthreads();
#pragma unroll
            for (int kk = 0; kk < 16; kk += 8) {
                uint32_t af[4][4], bf[4][2];
#pragma unroll
                for (int mi = 0; mi < 4; mi++) {
                    int mb = (wy * 64 + mi * 16 + gid) * PA + kk + tig;
                    af[mi][0] = T1[mb]; af[mi][1] = T1[mb + 8 * PA];
                    af[mi][2] = T1[mb + 4]; af[mi][3] = T1[mb + 8 * PA + 4];
                }
#pragma unroll
                for (int ni = 0; ni < 4; ni++) {
                    int nb = wx * 32 + ni * 8 + gid;
                    int sw = nb >> 3;
                    bf[ni][0] = T2[nb * PA + ((kk + tig) ^ sw)];
                    bf[ni][1] = T2[nb * PA + ((kk + tig + 4) ^ sw)];
                }
#pragma unroll
                for (int mi = 0; mi < 4; mi++)
#pragma unroll
                    for (int ni = 0; ni < 4; ni++)
                        mma_tf32(acc[mi][ni], af[mi], bf[ni]);
            }
        }
    }

    // ---- fused group-norm + swish gate (fp16 out) ----
    float* Ysm = (float*)dsm;
#pragma unroll
    for (int mi = 0; mi < 4; mi++) {
        int r0 = wy * 64 + mi * 16 + gid, r1 = r0 + 8;
#pragma unroll
        for (int ni = 0; ni < 4; ni++) {
            int c0 = wx * 32 + ni * 8 + tig * 2;
            Ysm[r0 * PAsm + c0]     = acc[mi][ni][0];
            Ysm[r0 * PAsm + c0 + 1] = acc[mi][ni][1];
            Ysm[r1 * PAsm + c0]     = acc[mi][ni][2];
            Ysm[r1 * PAsm + c0 + 1] = acc[mi][ni][3];
        }
    }
    __syncthreads();
    const float* gnwh = gnw + n * HDq;
    const float* gnbh = gnb + n * HDq;
#pragma unroll 1
    for (int rr = 0; rr < 16; rr++) {
        int row = warp * 16 + rr;
        float y[4];
#pragma unroll
        for (int i = 0; i < 4; i++) y[i] = Ysm[row * PAsm + lane + 32 * i];
        float s = y[0] + y[1] + y[2] + y[3];
#pragma unroll
        for (int o = 16; o; o >>= 1) s += __shfl_xor_sync(0xffffffffu, s, o);
        float m = s * (1.f / HDq);
        float s2 = 0.f;
#pragma unroll
        for (int i = 0; i < 4; i++) { y[i] -= m; s2 += y[i] * y[i]; }
#pragma unroll
        for (int o = 16; o; o >>= 1) s2 += __shfl_xor_sync(0xffffffffu, s2, o);
        float inv = rsqrtf(s2 * (1.f / HDq) + EPSq);
        long srow = (long)b * Sq + c * CHq + row;
        const __half* gp = QKVG + srow * QS + GOFF + n * HDq;
        __half* op = outG + srow * Hq + n * HDq;
#pragma unroll
        for (int i = 0; i < 4; i++) {
            int d = lane + 32 * i;
            float g = __half2float(gp[d]);
            float yn = y[i] * inv * gnwh[d] + gnbh[d];
            op[d] = __float2half((g / (1.f + expf(-g))) * yn);
        }
    }
}

// ============================================================================
extern "C" void kernel_launch(void* const* d_in, const int* in_sizes, int n_in,
                              void* d_out, int out_size) {
    const float* Xin  = (const float*)d_in[0];
    const float* WQ   = (const float*)d_in[1];
    const float* WK   = (const float*)d_in[2];
    const float* WV   = (const float*)d_in[3];
    const float* WG   = (const float*)d_in[4];
    const float* WO   = (const float*)d_in[5];
    const float* gn_w = (const float*)d_in[6];
    const float* gn_b = (const float*)d_in[7];
    const float* ln1w = (const float*)d_in[8];
    const float* ln1b = (const float*)d_in[9];
    const float* ln2w = (const float*)d_in[10];
    const float* ln2b = (const float*)d_in[11];
    const float* fw1  = (const float*)d_in[12];
    const float* fb1  = (const float*)d_in[13];
    const float* fw2  = (const float*)d_in[14];
    const float* fb2  = (const float*)d_in[15];
    float* out = (float*)d_out;

    float *pY, *pX, *pM, *pSt;
    float2* pXpos;
    __half *pQKVGh, *pXnH, *pGatedH, *pHnH, *pHfH, *pXH;
    __half *pWcat, *pWOTh, *pW1Th, *pW2Th;
    cudaGetSymbolAddress((void**)&pQKVGh, g_QKVGh);
    cudaGetSymbolAddress((void**)&pY, g_Y);
    cudaGetSymbolAddress((void**)&pX, g_X);
    cudaGetSymbolAddress((void**)&pM, g_M);
    cudaGetSymbolAddress((void**)&pSt, g_St);
    cudaGetSymbolAddress((void**)&pXpos, g_xposT);
    cudaGetSymbolAddress((void**)&pXnH, g_XnH);
    cudaGetSymbolAddress((void**)&pGatedH, g_GatedH);
    cudaGetSymbolAddress((void**)&pHnH, g_HnH);
    cudaGetSymbolAddress((void**)&pHfH, g_HfH);
    cudaGetSymbolAddress((void**)&pXH, g_XH);
    cudaGetSymbolAddress((void**)&pWcat, g_Wcat);
    cudaGetSymbolAddress((void**)&pWOTh, g_WOTh);
    cudaGetSymbolAddress((void**)&pW1Th, g_W1Th);
    cudaGetSymbolAddress((void**)&pW2Th, g_W2Th);

    const int smemCO = (128 * PAsm + 2 * 128 * PA) * 4;
    cudaFuncSetAttribute(chunk_out_kernel, cudaFuncAttributeMaxDynamicSharedMemorySize, smemCO);
    cudaFuncSetAttribute(h_gemm_kernel, cudaFuncAttributeMaxDynamicSharedMemorySize, GEMM_SMEM);

    xpos_table_kernel<<<(2 * Sq * 64 + 255) / 256, 256>>>(pXpos);
    packqkv_kernel<<<dim3(4, 16, 12), 256>>>(WQ, WK, WV, pWcat);
    transposeh_kernel<<<dim3(16, 16, 3), 256>>>(WG, pWcat + (long)GOFF * Hq, Hq, Hq,
        (long)Hq * Hq, (long)QS * Hq);
    transposeh_kernel<<<dim3(16, 16, 3), 256>>>(WO, pWOTh, Hq, Hq, (long)Hq * Hq, (long)Hq * Hq);
    transposeh_kernel<<<dim3(64, 16, 3), 256>>>(fw1, pW1Th, Hq, FFNq, (long)Hq * FFNq, (long)Hq * FFNq);
    transposeh_kernel<<<dim3(16, 64, 3), 256>>>(fw2, pW2Th, FFNq, Hq, (long)Hq * FFNq, (long)Hq * FFNq);

    const float* cur = Xin;
    for (int l = 0; l < Lq; l++) {
        ln_kernel<<<BSq / 8, 256>>>(cur, ln1w + (long)l * Hq, ln1b + (long)l * Hq, pXnH);
        h_gemm_kernel<<<dim3(QS / 128, BSq / 128, 1), 256, GEMM_SMEM>>>(
            pXnH, pWcat + (long)l * QS * Hq, nullptr, pQKVGh,
            Hq, Hq, Hq, QS, 0, 0, 0, nullptr, nullptr, 4);
        chunk_kv_kernel<<<Bq * NHq * NCq, 256>>>(pQKVGh, pM);
        scan_kernel<<<(Bq * NHq * HDq * HDq) / 256, 256>>>(pM, pSt);
        chunk_out_kernel<<<Bq * NHq * NCq, 256, smemCO>>>(pQKVGh, pSt,
            gn_w + (long)l * Hq, gn_b + (long)l * Hq, pGatedH);
        h_gemm_kernel<<<dim3(Hq / 128, BSq / 128, 1), 256, GEMM_SMEM>>>(
            pGatedH, pWOTh + (long)l * Hq * Hq, pY, nullptr,
            Hq, Hq, Hq, Hq, 0, 0, 0, nullptr, cur, 0);
        ln_kernel<<<BSq / 8, 256>>>(pY, ln2w + (long)l * Hq, ln2b + (long)l * Hq, pHnH);
        h_gemm_kernel<<<dim3(FFNq / 128, BSq / 128, 1), 256, GEMM_SMEM>>>(
            pHnH, pW1Th + (long)l * Hq * FFNq, nullptr, pHfH,
            Hq, Hq, Hq, FFNq, 0, 0, 0, fb1 + (long)l * FFNq, nullptr, 1);
        float* dst = (l == Lq - 1) ? out : pX;
        __half* dstH = (l == Lq - 1) ? pXH : nullptr;
        h_gemm_kernel<<<dim3(Hq / 128, BSq / 128, 1), 256, GEMM_SMEM>>>(
            pHfH, pW2Th + (long)l * Hq * FFNq, dst, dstH,
            FFNq, FFNq, FFNq, Hq, 0, 0, 0, fb2 + (long)l * Hq, pY, 0);
        cur = dst;
    }

    long nX = (long)BSq * Hq;
    // symmetric X @ X^T: lower-triangle tiles only, mirror writes
    h_gemm_kernel<<<dim3(136, 1, Bq), 256, GEMM_SMEM>>>(
        pXH, pXH, out + nX, nullptr,
        Hq, Hq, Hq, Sq,
        (long)Sq * Hq, (long)Sq * Hq, (long)Sq * Sq,
        nullptr, nullptr, 5);
}